// round 1
// baseline (speedup 1.0000x reference)
#include <cuda_runtime.h>
#include <cstdint>

#define N_NODES 50000
#define N_EDGES 800000
#define IN_FEATS 768
#define HIDDEN 256
#define OUT_FEATS 128

// ---------------- scratch (device globals; no allocation allowed) ----------
__device__ int   g_cnt[N_NODES];
__device__ int   g_off[N_NODES + 1];
__device__ int   g_cur[N_NODES];
__device__ int   g_csr_src[N_EDGES];
__device__ float g_dinv[N_NODES];
__device__ float g_H1 [N_NODES * HIDDEN];   // X @ W1 (pre-agg)
__device__ float g_H1a[N_NODES * HIDDEN];   // relu(agg(H1) + b1)
__device__ float g_H2 [N_NODES * OUT_FEATS];// H1a @ W2 (pre-agg)

// ---------------- CSR build -------------------------------------------------
__global__ void k_zero_cnt() {
    int i = blockIdx.x * blockDim.x + threadIdx.x;
    if (i < N_NODES) g_cnt[i] = 0;
}

__global__ void k_count(const int* __restrict__ dst) {
    int e = blockIdx.x * blockDim.x + threadIdx.x;
    if (e < N_EDGES) atomicAdd(&g_cnt[dst[e]], 1);
}

// single-block exclusive scan over 50000 counts; also fills g_cur and g_dinv
__global__ void k_scan() {
    __shared__ int partial[1024];
    int t = threadIdx.x;
    const int CH = (N_NODES + 1023) / 1024;  // 49
    int begin = t * CH;
    int end = begin + CH; if (end > N_NODES) end = N_NODES;
    int s = 0;
    for (int i = begin; i < end; i++) s += g_cnt[i];
    partial[t] = s;
    __syncthreads();
    // Kogge-Stone inclusive scan over 1024 partials
    for (int ofs = 1; ofs < 1024; ofs <<= 1) {
        int v = (t >= ofs) ? partial[t - ofs] : 0;
        __syncthreads();
        partial[t] += v;
        __syncthreads();
    }
    int run = (t == 0) ? 0 : partial[t - 1];
    for (int i = begin; i < end; i++) {
        g_off[i] = run;
        g_cur[i] = run;
        int c = g_cnt[i];
        g_dinv[i] = rsqrtf((float)(c + 1));   // +1 self loop
        run += c;
    }
    if (t == 0) g_off[N_NODES] = N_EDGES;
}

__global__ void k_fill(const int* __restrict__ src, const int* __restrict__ dst) {
    int e = blockIdx.x * blockDim.x + threadIdx.x;
    if (e < N_EDGES) {
        int d = dst[e];
        int p = atomicAdd(&g_cur[d], 1);
        g_csr_src[p] = src[e];
    }
}

// ---------------- SGEMM (128x128x8, 8x8 per thread, fp32) ------------------
template <int BM, int BN, int BK, int TM, int TN>
__global__ __launch_bounds__(256) void k_sgemm(
    int M, int N, int K,
    const float* __restrict__ A, const float* __restrict__ B,
    float* __restrict__ C)
{
    __shared__ float As[BK][BM];
    __shared__ float Bs[BK][BN];
    const int tid = threadIdx.x;                  // 256 threads
    const int blockRow = blockIdx.x * BM;
    const int blockCol = blockIdx.y * BN;
    const int tcol = tid % (BN / TN);             // 0..15
    const int trow = tid / (BN / TN);             // 0..15
    const int aRow = tid / (BK / 4);              // 0..127
    const int aCol = (tid % (BK / 4)) * 4;        // 0 or 4
    const int bRow = tid / (BN / 4);              // 0..7
    const int bCol = (tid % (BN / 4)) * 4;

    float acc[TM][TN];
#pragma unroll
    for (int i = 0; i < TM; i++)
#pragma unroll
        for (int j = 0; j < TN; j++) acc[i][j] = 0.f;

    float regM[TM], regN[TN];

    for (int k0 = 0; k0 < K; k0 += BK) {
        float4 a4;
        int gr = blockRow + aRow;
        if (gr < M) a4 = *reinterpret_cast<const float4*>(&A[(size_t)gr * K + k0 + aCol]);
        else        a4 = make_float4(0.f, 0.f, 0.f, 0.f);
        As[aCol + 0][aRow] = a4.x;
        As[aCol + 1][aRow] = a4.y;
        As[aCol + 2][aRow] = a4.z;
        As[aCol + 3][aRow] = a4.w;

        float4 b4 = *reinterpret_cast<const float4*>(&B[(size_t)(k0 + bRow) * N + blockCol + bCol]);
        *reinterpret_cast<float4*>(&Bs[bRow][bCol]) = b4;
        __syncthreads();

#pragma unroll
        for (int k = 0; k < BK; k++) {
#pragma unroll
            for (int i = 0; i < TM; i++) regM[i] = As[k][trow * TM + i];
#pragma unroll
            for (int j = 0; j < TN; j++) regN[j] = Bs[k][tcol * TN + j];
#pragma unroll
            for (int i = 0; i < TM; i++)
#pragma unroll
                for (int j = 0; j < TN; j++)
                    acc[i][j] += regM[i] * regN[j];
        }
        __syncthreads();
    }

#pragma unroll
    for (int i = 0; i < TM; i++) {
        int gr = blockRow + trow * TM + i;
        if (gr >= M) continue;
#pragma unroll
        for (int j = 0; j < TN; j += 4) {
            *reinterpret_cast<float4*>(&C[(size_t)gr * N + blockCol + tcol * TN + j]) =
                make_float4(acc[i][j], acc[i][j + 1], acc[i][j + 2], acc[i][j + 3]);
        }
    }
}

// ---------------- aggregation: warp-per-node gather-reduce -----------------
// layer 1: F=256 (two float4 per lane), + b1, relu -> g_H1a
__global__ __launch_bounds__(128) void k_agg1(const float* __restrict__ b1) {
    int node = blockIdx.x * 4 + (threadIdx.x >> 5);
    if (node >= N_NODES) return;
    int lane = threadIdx.x & 31;
    float wd = g_dinv[node];
    float sw = wd * wd;

    const float* hn = &g_H1[(size_t)node * HIDDEN];
    float4 v0 = *reinterpret_cast<const float4*>(&hn[lane * 4]);
    float4 v1 = *reinterpret_cast<const float4*>(&hn[128 + lane * 4]);
    float4 a0 = make_float4(v0.x * sw, v0.y * sw, v0.z * sw, v0.w * sw);
    float4 a1 = make_float4(v1.x * sw, v1.y * sw, v1.z * sw, v1.w * sw);

    int beg = g_off[node], end = g_off[node + 1];
    int i = beg;
    for (; i + 1 < end; i += 2) {
        int s0 = g_csr_src[i];
        int s1 = g_csr_src[i + 1];
        float w0 = g_dinv[s0] * wd;
        float w1 = g_dinv[s1] * wd;
        const float* h0 = &g_H1[(size_t)s0 * HIDDEN];
        const float* h1 = &g_H1[(size_t)s1 * HIDDEN];
        float4 p0 = *reinterpret_cast<const float4*>(&h0[lane * 4]);
        float4 p1 = *reinterpret_cast<const float4*>(&h0[128 + lane * 4]);
        float4 q0 = *reinterpret_cast<const float4*>(&h1[lane * 4]);
        float4 q1 = *reinterpret_cast<const float4*>(&h1[128 + lane * 4]);
        a0.x += p0.x * w0; a0.y += p0.y * w0; a0.z += p0.z * w0; a0.w += p0.w * w0;
        a1.x += p1.x * w0; a1.y += p1.y * w0; a1.z += p1.z * w0; a1.w += p1.w * w0;
        a0.x += q0.x * w1; a0.y += q0.y * w1; a0.z += q0.z * w1; a0.w += q0.w * w1;
        a1.x += q1.x * w1; a1.y += q1.y * w1; a1.z += q1.z * w1; a1.w += q1.w * w1;
    }
    if (i < end) {
        int s0 = g_csr_src[i];
        float w0 = g_dinv[s0] * wd;
        const float* h0 = &g_H1[(size_t)s0 * HIDDEN];
        float4 p0 = *reinterpret_cast<const float4*>(&h0[lane * 4]);
        float4 p1 = *reinterpret_cast<const float4*>(&h0[128 + lane * 4]);
        a0.x += p0.x * w0; a0.y += p0.y * w0; a0.z += p0.z * w0; a0.w += p0.w * w0;
        a1.x += p1.x * w0; a1.y += p1.y * w0; a1.z += p1.z * w0; a1.w += p1.w * w0;
    }

    float4 bb0 = *reinterpret_cast<const float4*>(&b1[lane * 4]);
    float4 bb1 = *reinterpret_cast<const float4*>(&b1[128 + lane * 4]);
    float* out = &g_H1a[(size_t)node * HIDDEN];
    float4 r0 = make_float4(fmaxf(a0.x + bb0.x, 0.f), fmaxf(a0.y + bb0.y, 0.f),
                            fmaxf(a0.z + bb0.z, 0.f), fmaxf(a0.w + bb0.w, 0.f));
    float4 r1 = make_float4(fmaxf(a1.x + bb1.x, 0.f), fmaxf(a1.y + bb1.y, 0.f),
                            fmaxf(a1.z + bb1.z, 0.f), fmaxf(a1.w + bb1.w, 0.f));
    *reinterpret_cast<float4*>(&out[lane * 4]) = r0;
    *reinterpret_cast<float4*>(&out[128 + lane * 4]) = r1;
}

// layer 2: F=128 (one float4 per lane), + b2, no relu -> d_out
__global__ __launch_bounds__(128) void k_agg2(const float* __restrict__ b2,
                                              float* __restrict__ out) {
    int node = blockIdx.x * 4 + (threadIdx.x >> 5);
    if (node >= N_NODES) return;
    int lane = threadIdx.x & 31;
    float wd = g_dinv[node];
    float sw = wd * wd;

    const float* hn = &g_H2[(size_t)node * OUT_FEATS];
    float4 v0 = *reinterpret_cast<const float4*>(&hn[lane * 4]);
    float4 a0 = make_float4(v0.x * sw, v0.y * sw, v0.z * sw, v0.w * sw);

    int beg = g_off[node], end = g_off[node + 1];
    int i = beg;
    for (; i + 1 < end; i += 2) {
        int s0 = g_csr_src[i];
        int s1 = g_csr_src[i + 1];
        float w0 = g_dinv[s0] * wd;
        float w1 = g_dinv[s1] * wd;
        float4 p0 = *reinterpret_cast<const float4*>(&g_H2[(size_t)s0 * OUT_FEATS + lane * 4]);
        float4 q0 = *reinterpret_cast<const float4*>(&g_H2[(size_t)s1 * OUT_FEATS + lane * 4]);
        a0.x += p0.x * w0; a0.y += p0.y * w0; a0.z += p0.z * w0; a0.w += p0.w * w0;
        a0.x += q0.x * w1; a0.y += q0.y * w1; a0.z += q0.z * w1; a0.w += q0.w * w1;
    }
    if (i < end) {
        int s0 = g_csr_src[i];
        float w0 = g_dinv[s0] * wd;
        float4 p0 = *reinterpret_cast<const float4*>(&g_H2[(size_t)s0 * OUT_FEATS + lane * 4]);
        a0.x += p0.x * w0; a0.y += p0.y * w0; a0.z += p0.z * w0; a0.w += p0.w * w0;
    }

    float4 bb = *reinterpret_cast<const float4*>(&b2[lane * 4]);
    *reinterpret_cast<float4*>(&out[(size_t)node * OUT_FEATS + lane * 4]) =
        make_float4(a0.x + bb.x, a0.y + bb.y, a0.z + bb.z, a0.w + bb.w);
}

// ---------------- launch -----------------------------------------------------
extern "C" void kernel_launch(void* const* d_in, const int* in_sizes, int n_in,
                              void* d_out, int out_size) {
    const float* x    = (const float*)d_in[0];
    const int*   ei   = (const int*)d_in[1];      // [2, E]: row0=src, row1=dst
    const float* W1   = (const float*)d_in[2];
    const float* b1   = (const float*)d_in[3];
    const float* W2   = (const float*)d_in[4];
    const float* b2   = (const float*)d_in[5];
    float* out = (float*)d_out;

    const int* src = ei;
    const int* dst = ei + N_EDGES;

    float* H1  = nullptr; cudaGetSymbolAddress((void**)&H1,  g_H1);
    float* H1a = nullptr; cudaGetSymbolAddress((void**)&H1a, g_H1a);
    float* H2  = nullptr; cudaGetSymbolAddress((void**)&H2,  g_H2);

    // CSR build
    k_zero_cnt<<<(N_NODES + 255) / 256, 256>>>();
    k_count<<<(N_EDGES + 255) / 256, 256>>>(dst);
    k_scan<<<1, 1024>>>();
    k_fill<<<(N_EDGES + 255) / 256, 256>>>(src, dst);

    // layer 1: GEMM then gather-aggregate
    {
        dim3 grid((N_NODES + 127) / 128, HIDDEN / 128);
        k_sgemm<128, 128, 8, 8, 8><<<grid, 256>>>(N_NODES, HIDDEN, IN_FEATS, x, W1, H1);
    }
    k_agg1<<<(N_NODES + 3) / 4, 128>>>(b1);

    // layer 2
    {
        dim3 grid((N_NODES + 127) / 128, OUT_FEATS / 128);
        k_sgemm<128, 128, 8, 8, 8><<<grid, 256>>>(N_NODES, OUT_FEATS, HIDDEN, H1a, W2, H2);
    }
    k_agg2<<<(N_NODES + 3) / 4, 128>>>(b2, out);
}

// round 3
// speedup vs baseline: 1.7687x; 1.7687x over previous
#include <cuda_runtime.h>
#include <cuda_bf16.h>
#include <cstdint>

#define N_NODES 50000
#define M_PAD   50048              // N_NODES padded to multiple of 128
#define N_EDGES 800000
#define IN_FEATS 768
#define HIDDEN 256
#define OUT_FEATS 128

// ------------------------------------------------------------------------
// device scratch (no allocation allowed)
// ------------------------------------------------------------------------
__device__ int   g_cnt[N_NODES];
__device__ int   g_off[N_NODES + 1];
__device__ int   g_cur[N_NODES];
__device__ int   g_csr_src[N_EDGES];
__device__ float g_dinv[N_NODES];

__device__ __nv_bfloat16 g_xhi[(size_t)M_PAD * IN_FEATS];
__device__ __nv_bfloat16 g_xlo[(size_t)M_PAD * IN_FEATS];
__device__ __nv_bfloat16 g_w1hi[HIDDEN * IN_FEATS];   // W1^T  [256][768]
__device__ __nv_bfloat16 g_w1lo[HIDDEN * IN_FEATS];
__device__ __nv_bfloat16 g_h1hi[(size_t)M_PAD * HIDDEN];
__device__ __nv_bfloat16 g_h1lo[(size_t)M_PAD * HIDDEN];
__device__ __nv_bfloat16 g_w2hi[OUT_FEATS * HIDDEN];  // W2^T  [128][256]
__device__ __nv_bfloat16 g_w2lo[OUT_FEATS * HIDDEN];

__device__ float g_H1 [(size_t)M_PAD * HIDDEN];       // X @ W1 (padded rows)
__device__ float g_H1a[(size_t)N_NODES * HIDDEN];     // relu(agg + b1)
__device__ float g_H2 [(size_t)M_PAD * OUT_FEATS];    // H1a @ W2 (padded rows)

// ------------------------------------------------------------------------
// PTX helpers (plain sm_90/sm_80-level instructions only — the harness
// PTX target is compute_103 WITHOUT the 'a' feature set, so no tcgen05)
// ------------------------------------------------------------------------
__device__ __forceinline__ uint32_t smem_u32(const void* p) {
    uint32_t a;
    asm("{ .reg .u64 t; cvta.to.shared.u64 t, %1; cvt.u32.u64 %0, t; }"
        : "=r"(a) : "l"(p));
    return a;
}

__device__ __forceinline__ void cp16(uint32_t dst, const void* src) {
    asm volatile("cp.async.cg.shared.global [%0], [%1], 16;" :: "r"(dst), "l"(src) : "memory");
}

__device__ __forceinline__ void ldsm_x4(uint32_t* r, uint32_t addr) {
    asm volatile("ldmatrix.sync.aligned.m8n8.x4.shared.b16 {%0,%1,%2,%3}, [%4];"
                 : "=r"(r[0]), "=r"(r[1]), "=r"(r[2]), "=r"(r[3]) : "r"(addr));
}

__device__ __forceinline__ void mma_bf16(float* d, const uint32_t* a, const uint32_t* b) {
    asm volatile(
        "mma.sync.aligned.m16n8k16.row.col.f32.bf16.bf16.f32 "
        "{%0,%1,%2,%3}, {%4,%5,%6,%7}, {%8,%9}, {%0,%1,%2,%3};"
        : "+f"(d[0]), "+f"(d[1]), "+f"(d[2]), "+f"(d[3])
        : "r"(a[0]), "r"(a[1]), "r"(a[2]), "r"(a[3]), "r"(b[0]), "r"(b[1]));
}

// ------------------------------------------------------------------------
// CSR build
// ------------------------------------------------------------------------
__global__ void k_zero_cnt() {
    int i = blockIdx.x * blockDim.x + threadIdx.x;
    if (i < N_NODES) g_cnt[i] = 0;
}

__global__ void k_count(const int* __restrict__ dst) {
    int e = blockIdx.x * blockDim.x + threadIdx.x;
    if (e < N_EDGES) atomicAdd(&g_cnt[dst[e]], 1);
}

__global__ void k_scan() {
    __shared__ int partial[1024];
    int t = threadIdx.x;
    const int CH = (N_NODES + 1023) / 1024;
    int begin = t * CH;
    int end = begin + CH; if (end > N_NODES) end = N_NODES;
    int s = 0;
    for (int i = begin; i < end; i++) s += g_cnt[i];
    partial[t] = s;
    __syncthreads();
    for (int ofs = 1; ofs < 1024; ofs <<= 1) {
        int v = (t >= ofs) ? partial[t - ofs] : 0;
        __syncthreads();
        partial[t] += v;
        __syncthreads();
    }
    int run = (t == 0) ? 0 : partial[t - 1];
    for (int i = begin; i < end; i++) {
        g_off[i] = run;
        g_cur[i] = run;
        int c = g_cnt[i];
        g_dinv[i] = rsqrtf((float)(c + 1));
        run += c;
    }
    if (t == 0) g_off[N_NODES] = N_EDGES;
}

__global__ void k_fill(const int* __restrict__ src, const int* __restrict__ dst) {
    int e = blockIdx.x * blockDim.x + threadIdx.x;
    if (e < N_EDGES) {
        int d = dst[e];
        int p = atomicAdd(&g_cur[d], 1);
        g_csr_src[p] = src[e];
    }
}

// ------------------------------------------------------------------------
// fp32 -> bf16 (hi, lo) split kernels
// ------------------------------------------------------------------------
template <int F>
__global__ void k_split(const float* __restrict__ src, int nrows_valid,
                        __nv_bfloat16* __restrict__ hi_out,
                        __nv_bfloat16* __restrict__ lo_out) {
    size_t i4 = (size_t)blockIdx.x * blockDim.x + threadIdx.x;
    const size_t total4 = (size_t)M_PAD * F / 4;
    if (i4 >= total4) return;
    size_t i = i4 * 4;
    int row = (int)(i / F);
    float4 v = make_float4(0.f, 0.f, 0.f, 0.f);
    if (row < nrows_valid) v = *reinterpret_cast<const float4*>(src + i);
    float a[4] = {v.x, v.y, v.z, v.w};
    __nv_bfloat16 h[4], l[4];
#pragma unroll
    for (int t = 0; t < 4; t++) {
        h[t] = __float2bfloat16(a[t]);
        l[t] = __float2bfloat16(a[t] - __bfloat162float(h[t]));
    }
    *reinterpret_cast<__nv_bfloat162*>(hi_out + i)     = __halves2bfloat162(h[0], h[1]);
    *reinterpret_cast<__nv_bfloat162*>(hi_out + i + 2) = __halves2bfloat162(h[2], h[3]);
    *reinterpret_cast<__nv_bfloat162*>(lo_out + i)     = __halves2bfloat162(l[0], l[1]);
    *reinterpret_cast<__nv_bfloat162*>(lo_out + i + 2) = __halves2bfloat162(l[2], l[3]);
}

// transpose + split for weights: W[K][N] -> Wt[N][K] hi/lo
__global__ void k_split_wT(const float* __restrict__ W, int K, int N,
                           __nv_bfloat16* __restrict__ hi,
                           __nv_bfloat16* __restrict__ lo) {
    int idx = blockIdx.x * blockDim.x + threadIdx.x;
    if (idx >= N * K) return;
    int n = idx / K, k = idx % K;
    float v = W[(size_t)k * N + n];
    __nv_bfloat16 h = __float2bfloat16(v);
    hi[idx] = h;
    lo[idx] = __float2bfloat16(v - __bfloat162float(h));
}

// ------------------------------------------------------------------------
// bf16-split GEMM via mma.sync m16n8k16:
//   C[M_PAD, Ncols] = A * B^T  (3-term: AhBh + AlBh + AhBl)
// A*: [M_PAD, KTOT] bf16; B*: [Ncols, KTOT] bf16 (weights pre-transposed)
// CTA tile 128x128, BK=32, 256 threads (8 warps, warp tile 32x64),
// double-buffered cp.async; smem rows padded to 80B for conflict-free ldsm.
// ------------------------------------------------------------------------
static constexpr int ROWB   = 80;        // 32 bf16 (64B) + 16B pad
static constexpr int TILEB  = 128 * ROWB;           // 10240 per operand tile
static constexpr int STAGEB = 4 * TILEB;            // Ahi,Alo,Bhi,Blo = 40960
static constexpr int SMEMB  = 2 * STAGEB;           // 81920

template <int KTOT>
__device__ __forceinline__ void load_stage(
    uint32_t sb, int tid, int kc, int m0, int n0,
    const __nv_bfloat16* __restrict__ Ahi, const __nv_bfloat16* __restrict__ Alo,
    const __nv_bfloat16* __restrict__ Bhi, const __nv_bfloat16* __restrict__ Blo)
{
    const int k0 = kc * 32;
#pragma unroll
    for (int j = 0; j < 8; j++) {
        int linear = j * 256 + tid;
        int tile   = linear >> 9;        // /512 : 0 Ahi, 1 Alo, 2 Bhi, 3 Blo
        int within = linear & 511;
        int row    = within >> 2;
        int chunk  = within & 3;
        const __nv_bfloat16* base = (tile == 0) ? Ahi : (tile == 1) ? Alo
                                   : (tile == 2) ? Bhi : Blo;
        int grow = ((tile < 2) ? m0 : n0) + row;
        const void* g = base + (size_t)grow * KTOT + k0 + chunk * 8;
        cp16(sb + tile * TILEB + row * ROWB + chunk * 16, g);
    }
    asm volatile("cp.async.commit_group;" ::: "memory");
}

template <int KTOT>
__global__ __launch_bounds__(256, 2) void k_mma(
    const __nv_bfloat16* __restrict__ Ahi, const __nv_bfloat16* __restrict__ Alo,
    const __nv_bfloat16* __restrict__ Bhi, const __nv_bfloat16* __restrict__ Blo,
    float* __restrict__ C, int ldc)
{
    constexpr int NC = KTOT / 32;
    extern __shared__ __align__(128) char smem[];
    const uint32_t sb0 = smem_u32(smem);
    const int tid  = threadIdx.x;
    const int lane = tid & 31;
    const int wid  = tid >> 5;
    const int wm   = wid & 3;        // 4 warps down M (32 rows each)
    const int wn   = wid >> 2;       // 2 warps across N (64 cols each)
    const int m0 = blockIdx.y * 128, n0 = blockIdx.x * 128;

    float acc[2][8][4];
#pragma unroll
    for (int i = 0; i < 2; i++)
#pragma unroll
        for (int j = 0; j < 8; j++)
#pragma unroll
            for (int q = 0; q < 4; q++) acc[i][j][q] = 0.f;

    const int g = lane >> 3;         // ldmatrix group 0..3
    const int r = lane & 7;

    load_stage<KTOT>(sb0, tid, 0, m0, n0, Ahi, Alo, Bhi, Blo);

    for (int c = 0; c < NC; c++) {
        if (c + 1 < NC) {
            load_stage<KTOT>(sb0 + ((c + 1) & 1) * STAGEB, tid, c + 1, m0, n0,
                             Ahi, Alo, Bhi, Blo);
            asm volatile("cp.async.wait_group 1;" ::: "memory");
        } else {
            asm volatile("cp.async.wait_group 0;" ::: "memory");
        }
        __syncthreads();

        const uint32_t sb = sb0 + (c & 1) * STAGEB;
#pragma unroll
        for (int kk = 0; kk < 2; kk++) {
            uint32_t ahi[2][4], alo[2][4];
#pragma unroll
            for (int ms = 0; ms < 2; ms++) {
                uint32_t arow = wm * 32 + ms * 16 + ((g & 1) << 3) + r;
                uint32_t aoff = arow * ROWB + kk * 32 + ((g >> 1) << 4);
                ldsm_x4(ahi[ms], sb + aoff);
                ldsm_x4(alo[ms], sb + TILEB + aoff);
            }
#pragma unroll
            for (int nb2 = 0; nb2 < 4; nb2++) {
                uint32_t nrow = wn * 64 + nb2 * 16 + ((g >> 1) << 3) + r;
                uint32_t boff = nrow * ROWB + kk * 32 + ((g & 1) << 4);
                uint32_t bh[4], bl[4];
                ldsm_x4(bh, sb + 2 * TILEB + boff);
                ldsm_x4(bl, sb + 3 * TILEB + boff);
#pragma unroll
                for (int ms = 0; ms < 2; ms++) {
#pragma unroll
                    for (int h = 0; h < 2; h++) {
                        mma_bf16(acc[ms][nb2 * 2 + h], ahi[ms], &bh[h * 2]);
                        mma_bf16(acc[ms][nb2 * 2 + h], alo[ms], &bh[h * 2]);
                        mma_bf16(acc[ms][nb2 * 2 + h], ahi[ms], &bl[h * 2]);
                    }
                }
            }
        }
        __syncthreads();
    }

    // epilogue: fragment (t/4 -> row, t%4 -> col pair)
#pragma unroll
    for (int ms = 0; ms < 2; ms++) {
        int grow = m0 + wm * 32 + ms * 16 + (lane >> 2);
#pragma unroll
        for (int nb = 0; nb < 8; nb++) {
            int gcol = n0 + wn * 64 + nb * 8 + (lane & 3) * 2;
            *reinterpret_cast<float2*>(&C[(size_t)grow * ldc + gcol]) =
                make_float2(acc[ms][nb][0], acc[ms][nb][1]);
            *reinterpret_cast<float2*>(&C[(size_t)(grow + 8) * ldc + gcol]) =
                make_float2(acc[ms][nb][2], acc[ms][nb][3]);
        }
    }
}

// ------------------------------------------------------------------------
// aggregation: warp-per-node gather-reduce (fp32)
// ------------------------------------------------------------------------
__global__ __launch_bounds__(128) void k_agg1(const float* __restrict__ b1) {
    int node = blockIdx.x * 4 + (threadIdx.x >> 5);
    if (node >= N_NODES) return;
    int lane = threadIdx.x & 31;
    float wd = g_dinv[node];
    float sw = wd * wd;

    const float* hn = &g_H1[(size_t)node * HIDDEN];
    float4 v0 = *reinterpret_cast<const float4*>(&hn[lane * 4]);
    float4 v1 = *reinterpret_cast<const float4*>(&hn[128 + lane * 4]);
    float4 a0 = make_float4(v0.x * sw, v0.y * sw, v0.z * sw, v0.w * sw);
    float4 a1 = make_float4(v1.x * sw, v1.y * sw, v1.z * sw, v1.w * sw);

    int beg = g_off[node], end = g_off[node + 1];
    int i = beg;
    for (; i + 1 < end; i += 2) {
        int s0 = g_csr_src[i];
        int s1 = g_csr_src[i + 1];
        float w0 = g_dinv[s0] * wd;
        float w1 = g_dinv[s1] * wd;
        const float* h0 = &g_H1[(size_t)s0 * HIDDEN];
        const float* h1 = &g_H1[(size_t)s1 * HIDDEN];
        float4 p0 = *reinterpret_cast<const float4*>(&h0[lane * 4]);
        float4 p1 = *reinterpret_cast<const float4*>(&h0[128 + lane * 4]);
        float4 q0 = *reinterpret_cast<const float4*>(&h1[lane * 4]);
        float4 q1 = *reinterpret_cast<const float4*>(&h1[128 + lane * 4]);
        a0.x += p0.x * w0; a0.y += p0.y * w0; a0.z += p0.z * w0; a0.w += p0.w * w0;
        a1.x += p1.x * w0; a1.y += p1.y * w0; a1.z += p1.z * w0; a1.w += p1.w * w0;
        a0.x += q0.x * w1; a0.y += q0.y * w1; a0.z += q0.z * w1; a0.w += q0.w * w1;
        a1.x += q1.x * w1; a1.y += q1.y * w1; a1.z += q1.z * w1; a1.w += q1.w * w1;
    }
    if (i < end) {
        int s0 = g_csr_src[i];
        float w0 = g_dinv[s0] * wd;
        const float* h0 = &g_H1[(size_t)s0 * HIDDEN];
        float4 p0 = *reinterpret_cast<const float4*>(&h0[lane * 4]);
        float4 p1 = *reinterpret_cast<const float4*>(&h0[128 + lane * 4]);
        a0.x += p0.x * w0; a0.y += p0.y * w0; a0.z += p0.z * w0; a0.w += p0.w * w0;
        a1.x += p1.x * w0; a1.y += p1.y * w0; a1.z += p1.z * w0; a1.w += p1.w * w0;
    }

    float4 bb0 = *reinterpret_cast<const float4*>(&b1[lane * 4]);
    float4 bb1 = *reinterpret_cast<const float4*>(&b1[128 + lane * 4]);
    float* out = &g_H1a[(size_t)node * HIDDEN];
    float4 r0 = make_float4(fmaxf(a0.x + bb0.x, 0.f), fmaxf(a0.y + bb0.y, 0.f),
                            fmaxf(a0.z + bb0.z, 0.f), fmaxf(a0.w + bb0.w, 0.f));
    float4 r1 = make_float4(fmaxf(a1.x + bb1.x, 0.f), fmaxf(a1.y + bb1.y, 0.f),
                            fmaxf(a1.z + bb1.z, 0.f), fmaxf(a1.w + bb1.w, 0.f));
    *reinterpret_cast<float4*>(&out[lane * 4]) = r0;
    *reinterpret_cast<float4*>(&out[128 + lane * 4]) = r1;
}

__global__ __launch_bounds__(128) void k_agg2(const float* __restrict__ b2,
                                              float* __restrict__ out) {
    int node = blockIdx.x * 4 + (threadIdx.x >> 5);
    if (node >= N_NODES) return;
    int lane = threadIdx.x & 31;
    float wd = g_dinv[node];
    float sw = wd * wd;

    const float* hn = &g_H2[(size_t)node * OUT_FEATS];
    float4 v0 = *reinterpret_cast<const float4*>(&hn[lane * 4]);
    float4 a0 = make_float4(v0.x * sw, v0.y * sw, v0.z * sw, v0.w * sw);

    int beg = g_off[node], end = g_off[node + 1];
    int i = beg;
    for (; i + 1 < end; i += 2) {
        int s0 = g_csr_src[i];
        int s1 = g_csr_src[i + 1];
        float w0 = g_dinv[s0] * wd;
        float w1 = g_dinv[s1] * wd;
        float4 p0 = *reinterpret_cast<const float4*>(&g_H2[(size_t)s0 * OUT_FEATS + lane * 4]);
        float4 q0 = *reinterpret_cast<const float4*>(&g_H2[(size_t)s1 * OUT_FEATS + lane * 4]);
        a0.x += p0.x * w0; a0.y += p0.y * w0; a0.z += p0.z * w0; a0.w += p0.w * w0;
        a0.x += q0.x * w1; a0.y += q0.y * w1; a0.z += q0.z * w1; a0.w += q0.w * w1;
    }
    if (i < end) {
        int s0 = g_csr_src[i];
        float w0 = g_dinv[s0] * wd;
        float4 p0 = *reinterpret_cast<const float4*>(&g_H2[(size_t)s0 * OUT_FEATS + lane * 4]);
        a0.x += p0.x * w0; a0.y += p0.y * w0; a0.z += p0.z * w0; a0.w += p0.w * w0;
    }

    float4 bb = *reinterpret_cast<const float4*>(&b2[lane * 4]);
    *reinterpret_cast<float4*>(&out[(size_t)node * OUT_FEATS + lane * 4]) =
        make_float4(a0.x + bb.x, a0.y + bb.y, a0.z + bb.z, a0.w + bb.w);
}

// ------------------------------------------------------------------------
// launch
// ------------------------------------------------------------------------
extern "C" void kernel_launch(void* const* d_in, const int* in_sizes, int n_in,
                              void* d_out, int out_size) {
    const float* x  = (const float*)d_in[0];
    const int*   ei = (const int*)d_in[1];
    const float* W1 = (const float*)d_in[2];
    const float* b1 = (const float*)d_in[3];
    const float* W2 = (const float*)d_in[4];
    const float* b2 = (const float*)d_in[5];
    float* out = (float*)d_out;

    const int* src = ei;
    const int* dst = ei + N_EDGES;

    __nv_bfloat16 *xhi, *xlo, *w1hi, *w1lo, *h1hi, *h1lo, *w2hi, *w2lo;
    float *H1, *H1a, *H2;
    cudaGetSymbolAddress((void**)&xhi,  g_xhi);
    cudaGetSymbolAddress((void**)&xlo,  g_xlo);
    cudaGetSymbolAddress((void**)&w1hi, g_w1hi);
    cudaGetSymbolAddress((void**)&w1lo, g_w1lo);
    cudaGetSymbolAddress((void**)&h1hi, g_h1hi);
    cudaGetSymbolAddress((void**)&h1lo, g_h1lo);
    cudaGetSymbolAddress((void**)&w2hi, g_w2hi);
    cudaGetSymbolAddress((void**)&w2lo, g_w2lo);
    cudaGetSymbolAddress((void**)&H1,  g_H1);
    cudaGetSymbolAddress((void**)&H1a, g_H1a);
    cudaGetSymbolAddress((void**)&H2,  g_H2);

    cudaFuncSetAttribute(k_mma<IN_FEATS>, cudaFuncAttributeMaxDynamicSharedMemorySize, SMEMB);
    cudaFuncSetAttribute(k_mma<HIDDEN>,   cudaFuncAttributeMaxDynamicSharedMemorySize, SMEMB);

    // CSR build
    k_zero_cnt<<<(N_NODES + 255) / 256, 256>>>();
    k_count<<<(N_EDGES + 255) / 256, 256>>>(dst);
    k_scan<<<1, 1024>>>();
    k_fill<<<(N_EDGES + 255) / 256, 256>>>(src, dst);

    // split inputs & weights to bf16 hi/lo
    {
        size_t total4 = (size_t)M_PAD * IN_FEATS / 4;
        k_split<IN_FEATS><<<(unsigned)((total4 + 255) / 256), 256>>>(x, N_NODES, xhi, xlo);
    }
    k_split_wT<<<(HIDDEN * IN_FEATS + 255) / 256, 256>>>(W1, IN_FEATS, HIDDEN, w1hi, w1lo);
    k_split_wT<<<(OUT_FEATS * HIDDEN + 255) / 256, 256>>>(W2, HIDDEN, OUT_FEATS, w2hi, w2lo);

    // layer 1: tensor-core GEMM then gather-aggregate
    k_mma<IN_FEATS><<<dim3(HIDDEN / 128, M_PAD / 128), 256, SMEMB>>>(
        xhi, xlo, w1hi, w1lo, H1, HIDDEN);
    k_agg1<<<(N_NODES + 3) / 4, 128>>>(b1);

    // split hidden, layer 2
    {
        size_t total4 = (size_t)M_PAD * HIDDEN / 4;
        k_split<HIDDEN><<<(unsigned)((total4 + 255) / 256), 256>>>(H1a, N_NODES, h1hi, h1lo);
    }
    k_mma<HIDDEN><<<dim3(OUT_FEATS / 128, M_PAD / 128), 256, SMEMB>>>(
        h1hi, h1lo, w2hi, w2lo, H2, OUT_FEATS);
    k_agg2<<<(N_NODES + 3) / 4, 128>>>(b2, out);
}

// round 4
// speedup vs baseline: 1.8184x; 1.0281x over previous
#include <cuda_runtime.h>
#include <cuda_bf16.h>
#include <cstdint>

#define N_NODES 50000
#define M_PAD   50048              // N_NODES padded to multiple of 128
#define N_EDGES 800000
#define IN_FEATS 768
#define HIDDEN 256
#define OUT_FEATS 128

// ------------------------------------------------------------------------
// device scratch (no allocation allowed; zero-initialized at module load)
// ------------------------------------------------------------------------
__device__ int   g_cnt[N_NODES];
__device__ int   g_off[N_NODES + 1];
__device__ int   g_cur[N_NODES];
__device__ int   g_csr_src[N_EDGES];
__device__ float g_dinv[N_NODES];

__device__ __nv_bfloat16 g_xhi[(size_t)M_PAD * IN_FEATS];
__device__ __nv_bfloat16 g_xlo[(size_t)M_PAD * IN_FEATS];
__device__ __nv_bfloat16 g_w1hi[HIDDEN * IN_FEATS];   // W1^T  [256][768]
__device__ __nv_bfloat16 g_w1lo[HIDDEN * IN_FEATS];
__device__ __nv_bfloat16 g_h1hi[(size_t)M_PAD * HIDDEN];  // pad rows stay 0
__device__ __nv_bfloat16 g_h1lo[(size_t)M_PAD * HIDDEN];
__device__ __nv_bfloat16 g_w2hi[OUT_FEATS * HIDDEN];  // W2^T  [128][256]
__device__ __nv_bfloat16 g_w2lo[OUT_FEATS * HIDDEN];

__device__ float g_H1 [(size_t)M_PAD * HIDDEN];       // X @ W1 (padded rows)
__device__ float g_H2 [(size_t)M_PAD * OUT_FEATS];    // agg(H1) @ W2

// ------------------------------------------------------------------------
// PTX helpers (plain sm_80/90-level: harness PTX target lacks the 'a' set)
// ------------------------------------------------------------------------
__device__ __forceinline__ uint32_t smem_u32(const void* p) {
    uint32_t a;
    asm("{ .reg .u64 t; cvta.to.shared.u64 t, %1; cvt.u32.u64 %0, t; }"
        : "=r"(a) : "l"(p));
    return a;
}

__device__ __forceinline__ void cp16(uint32_t dst, const void* src) {
    asm volatile("cp.async.cg.shared.global [%0], [%1], 16;" :: "r"(dst), "l"(src) : "memory");
}

__device__ __forceinline__ void ldsm_x4(uint32_t* r, uint32_t addr) {
    asm volatile("ldmatrix.sync.aligned.m8n8.x4.shared.b16 {%0,%1,%2,%3}, [%4];"
                 : "=r"(r[0]), "=r"(r[1]), "=r"(r[2]), "=r"(r[3]) : "r"(addr));
}

__device__ __forceinline__ void mma_bf16(float* d, const uint32_t* a, const uint32_t* b) {
    asm volatile(
        "mma.sync.aligned.m16n8k16.row.col.f32.bf16.bf16.f32 "
        "{%0,%1,%2,%3}, {%4,%5,%6,%7}, {%8,%9}, {%0,%1,%2,%3};"
        : "+f"(d[0]), "+f"(d[1]), "+f"(d[2]), "+f"(d[3])
        : "r"(a[0]), "r"(a[1]), "r"(a[2]), "r"(a[3]), "r"(b[0]), "r"(b[1]));
}

// ------------------------------------------------------------------------
// CSR build
// ------------------------------------------------------------------------
__global__ void k_zero_cnt() {
    int i = blockIdx.x * blockDim.x + threadIdx.x;
    if (i < N_NODES) g_cnt[i] = 0;
}

__global__ void k_count(const int* __restrict__ dst) {
    int e4 = blockIdx.x * blockDim.x + threadIdx.x;
    if (e4 * 4 < N_EDGES) {
        int4 d = *reinterpret_cast<const int4*>(dst + e4 * 4);
        atomicAdd(&g_cnt[d.x], 1);
        atomicAdd(&g_cnt[d.y], 1);
        atomicAdd(&g_cnt[d.z], 1);
        atomicAdd(&g_cnt[d.w], 1);
    }
}

__global__ void k_scan() {
    __shared__ int partial[1024];
    int t = threadIdx.x;
    const int CH = (N_NODES + 1023) / 1024;
    int begin = t * CH;
    int end = begin + CH; if (end > N_NODES) end = N_NODES;
    int s = 0;
    for (int i = begin; i < end; i++) s += g_cnt[i];
    partial[t] = s;
    __syncthreads();
    for (int ofs = 1; ofs < 1024; ofs <<= 1) {
        int v = (t >= ofs) ? partial[t - ofs] : 0;
        __syncthreads();
        partial[t] += v;
        __syncthreads();
    }
    int run = (t == 0) ? 0 : partial[t - 1];
    for (int i = begin; i < end; i++) {
        g_off[i] = run;
        g_cur[i] = run;
        int c = g_cnt[i];
        g_dinv[i] = rsqrtf((float)(c + 1));
        run += c;
    }
    if (t == 0) g_off[N_NODES] = N_EDGES;
}

__global__ void k_fill(const int* __restrict__ src, const int* __restrict__ dst) {
    int e4 = blockIdx.x * blockDim.x + threadIdx.x;
    if (e4 * 4 < N_EDGES) {
        int4 d = *reinterpret_cast<const int4*>(dst + e4 * 4);
        int4 s = *reinterpret_cast<const int4*>(src + e4 * 4);
        g_csr_src[atomicAdd(&g_cur[d.x], 1)] = s.x;
        g_csr_src[atomicAdd(&g_cur[d.y], 1)] = s.y;
        g_csr_src[atomicAdd(&g_cur[d.z], 1)] = s.z;
        g_csr_src[atomicAdd(&g_cur[d.w], 1)] = s.w;
    }
}

// ------------------------------------------------------------------------
// fp32 -> bf16 (hi, lo) split kernels
// ------------------------------------------------------------------------
template <int F>
__global__ void k_split(const float* __restrict__ src, int nrows_valid,
                        __nv_bfloat16* __restrict__ hi_out,
                        __nv_bfloat16* __restrict__ lo_out) {
    size_t i4 = (size_t)blockIdx.x * blockDim.x + threadIdx.x;
    const size_t total4 = (size_t)M_PAD * F / 4;
    if (i4 >= total4) return;
    size_t i = i4 * 4;
    int row = (int)(i / F);
    float4 v = make_float4(0.f, 0.f, 0.f, 0.f);
    if (row < nrows_valid) v = *reinterpret_cast<const float4*>(src + i);
    float a[4] = {v.x, v.y, v.z, v.w};
    __nv_bfloat16 h[4], l[4];
#pragma unroll
    for (int t = 0; t < 4; t++) {
        h[t] = __float2bfloat16(a[t]);
        l[t] = __float2bfloat16(a[t] - __bfloat162float(h[t]));
    }
    *reinterpret_cast<__nv_bfloat162*>(hi_out + i)     = __halves2bfloat162(h[0], h[1]);
    *reinterpret_cast<__nv_bfloat162*>(hi_out + i + 2) = __halves2bfloat162(h[2], h[3]);
    *reinterpret_cast<__nv_bfloat162*>(lo_out + i)     = __halves2bfloat162(l[0], l[1]);
    *reinterpret_cast<__nv_bfloat162*>(lo_out + i + 2) = __halves2bfloat162(l[2], l[3]);
}

// transpose + split for weights: W[K][N] -> Wt[N][K] hi/lo
__global__ void k_split_wT(const float* __restrict__ W, int K, int N,
                           __nv_bfloat16* __restrict__ hi,
                           __nv_bfloat16* __restrict__ lo) {
    int idx = blockIdx.x * blockDim.x + threadIdx.x;
    if (idx >= N * K) return;
    int n = idx / K, k = idx % K;
    float v = W[(size_t)k * N + n];
    __nv_bfloat16 h = __float2bfloat16(v);
    hi[idx] = h;
    lo[idx] = __float2bfloat16(v - __bfloat162float(h));
}

// ------------------------------------------------------------------------
// bf16-split GEMM via mma.sync m16n8k16:  C = A * B^T
// CTA tile 128x128, BK=32, 8 warps (warp tile 32x64), double-buffered
// cp.async, 80B-padded smem rows (conflict-free ldsm).
// MMA emission is term-major so consecutive MMAs hit independent accs.
// ------------------------------------------------------------------------
static constexpr int ROWB   = 80;
static constexpr int TILEB  = 128 * ROWB;           // 10240 per operand tile
static constexpr int STAGEB = 4 * TILEB;            // 40960
static constexpr int SMEMB  = 2 * STAGEB;           // 81920

template <int KTOT>
__device__ __forceinline__ void load_stage(
    uint32_t sb, int tid, int kc, int m0, int n0,
    const __nv_bfloat16* __restrict__ Ahi, const __nv_bfloat16* __restrict__ Alo,
    const __nv_bfloat16* __restrict__ Bhi, const __nv_bfloat16* __restrict__ Blo)
{
    const int k0 = kc * 32;
#pragma unroll
    for (int j = 0; j < 8; j++) {
        int linear = j * 256 + tid;
        int tile   = linear >> 9;
        int within = linear & 511;
        int row    = within >> 2;
        int chunk  = within & 3;
        const __nv_bfloat16* base = (tile == 0) ? Ahi : (tile == 1) ? Alo
                                   : (tile == 2) ? Bhi : Blo;
        int grow = ((tile < 2) ? m0 : n0) + row;
        const void* g = base + (size_t)grow * KTOT + k0 + chunk * 8;
        cp16(sb + tile * TILEB + row * ROWB + chunk * 16, g);
    }
    asm volatile("cp.async.commit_group;" ::: "memory");
}

template <int KTOT>
__global__ __launch_bounds__(256, 2) void k_mma(
    const __nv_bfloat16* __restrict__ Ahi, const __nv_bfloat16* __restrict__ Alo,
    const __nv_bfloat16* __restrict__ Bhi, const __nv_bfloat16* __restrict__ Blo,
    float* __restrict__ C, int ldc)
{
    constexpr int NC = KTOT / 32;
    extern __shared__ __align__(128) char smem[];
    const uint32_t sb0 = smem_u32(smem);
    const int tid  = threadIdx.x;
    const int lane = tid & 31;
    const int wid  = tid >> 5;
    const int wm   = wid & 3;
    const int wn   = wid >> 2;
    const int m0 = blockIdx.y * 128, n0 = blockIdx.x * 128;

    float acc[2][8][4];
#pragma unroll
    for (int i = 0; i < 2; i++)
#pragma unroll
        for (int j = 0; j < 8; j++)
#pragma unroll
            for (int q = 0; q < 4; q++) acc[i][j][q] = 0.f;

    const int g = lane >> 3;
    const int r = lane & 7;

    load_stage<KTOT>(sb0, tid, 0, m0, n0, Ahi, Alo, Bhi, Blo);

    for (int c = 0; c < NC; c++) {
        if (c + 1 < NC) {
            load_stage<KTOT>(sb0 + ((c + 1) & 1) * STAGEB, tid, c + 1, m0, n0,
                             Ahi, Alo, Bhi, Blo);
            asm volatile("cp.async.wait_group 1;" ::: "memory");
        } else {
            asm volatile("cp.async.wait_group 0;" ::: "memory");
        }
        __syncthreads();

        const uint32_t sb = sb0 + (c & 1) * STAGEB;
#pragma unroll
        for (int kk = 0; kk < 2; kk++) {
            uint32_t ahi[2][4], alo[2][4];
#pragma unroll
            for (int ms = 0; ms < 2; ms++) {
                uint32_t arow = wm * 32 + ms * 16 + ((g & 1) << 3) + r;
                uint32_t aoff = arow * ROWB + kk * 32 + ((g >> 1) << 4);
                ldsm_x4(ahi[ms], sb + aoff);
                ldsm_x4(alo[ms], sb + TILEB + aoff);
            }
#pragma unroll
            for (int nb2 = 0; nb2 < 4; nb2++) {
                uint32_t nrow = wn * 64 + nb2 * 16 + ((g >> 1) << 3) + r;
                uint32_t boff = nrow * ROWB + kk * 32 + ((g & 1) << 4);
                uint32_t bh[4], bl[4];
                ldsm_x4(bh, sb + 2 * TILEB + boff);
                ldsm_x4(bl, sb + 3 * TILEB + boff);
                // term-major emission: 4 independent accs between reuses
#pragma unroll
                for (int ms = 0; ms < 2; ms++)
#pragma unroll
                    for (int h = 0; h < 2; h++)
                        mma_bf16(acc[ms][nb2 * 2 + h], ahi[ms], &bh[h * 2]);
#pragma unroll
                for (int ms = 0; ms < 2; ms++)
#pragma unroll
                    for (int h = 0; h < 2; h++)
                        mma_bf16(acc[ms][nb2 * 2 + h], alo[ms], &bh[h * 2]);
#pragma unroll
                for (int ms = 0; ms < 2; ms++)
#pragma unroll
                    for (int h = 0; h < 2; h++)
                        mma_bf16(acc[ms][nb2 * 2 + h], ahi[ms], &bl[h * 2]);
            }
        }
        __syncthreads();
    }

#pragma unroll
    for (int ms = 0; ms < 2; ms++) {
        int grow = m0 + wm * 32 + ms * 16 + (lane >> 2);
#pragma unroll
        for (int nb = 0; nb < 8; nb++) {
            int gcol = n0 + wn * 64 + nb * 8 + (lane & 3) * 2;
            *reinterpret_cast<float2*>(&C[(size_t)grow * ldc + gcol]) =
                make_float2(acc[ms][nb][0], acc[ms][nb][1]);
            *reinterpret_cast<float2*>(&C[(size_t)(grow + 8) * ldc + gcol]) =
                make_float2(acc[ms][nb][2], acc[ms][nb][3]);
        }
    }
}

// ------------------------------------------------------------------------
// aggregation: warp-per-node gather-reduce (fp32)
// layer 1: + b1, relu, FUSED bf16 hi/lo split -> g_h1hi/g_h1lo
// ------------------------------------------------------------------------
__global__ __launch_bounds__(128) void k_agg1(const float* __restrict__ b1) {
    int node = blockIdx.x * 4 + (threadIdx.x >> 5);
    if (node >= N_NODES) return;
    int lane = threadIdx.x & 31;
    float wd = g_dinv[node];
    float sw = wd * wd;

    const float* hn = &g_H1[(size_t)node * HIDDEN];
    float4 v0 = *reinterpret_cast<const float4*>(&hn[lane * 4]);
    float4 v1 = *reinterpret_cast<const float4*>(&hn[128 + lane * 4]);
    float4 a0 = make_float4(v0.x * sw, v0.y * sw, v0.z * sw, v0.w * sw);
    float4 a1 = make_float4(v1.x * sw, v1.y * sw, v1.z * sw, v1.w * sw);

    int beg = g_off[node], end = g_off[node + 1];
    int i = beg;
    for (; i + 1 < end; i += 2) {
        int s0 = g_csr_src[i];
        int s1 = g_csr_src[i + 1];
        float w0 = g_dinv[s0] * wd;
        float w1 = g_dinv[s1] * wd;
        const float* h0 = &g_H1[(size_t)s0 * HIDDEN];
        const float* h1 = &g_H1[(size_t)s1 * HIDDEN];
        float4 p0 = *reinterpret_cast<const float4*>(&h0[lane * 4]);
        float4 p1 = *reinterpret_cast<const float4*>(&h0[128 + lane * 4]);
        float4 q0 = *reinterpret_cast<const float4*>(&h1[lane * 4]);
        float4 q1 = *reinterpret_cast<const float4*>(&h1[128 + lane * 4]);
        a0.x += p0.x * w0; a0.y += p0.y * w0; a0.z += p0.z * w0; a0.w += p0.w * w0;
        a1.x += p1.x * w0; a1.y += p1.y * w0; a1.z += p1.z * w0; a1.w += p1.w * w0;
        a0.x += q0.x * w1; a0.y += q0.y * w1; a0.z += q0.z * w1; a0.w += q0.w * w1;
        a1.x += q1.x * w1; a1.y += q1.y * w1; a1.z += q1.z * w1; a1.w += q1.w * w1;
    }
    if (i < end) {
        int s0 = g_csr_src[i];
        float w0 = g_dinv[s0] * wd;
        const float* h0 = &g_H1[(size_t)s0 * HIDDEN];
        float4 p0 = *reinterpret_cast<const float4*>(&h0[lane * 4]);
        float4 p1 = *reinterpret_cast<const float4*>(&h0[128 + lane * 4]);
        a0.x += p0.x * w0; a0.y += p0.y * w0; a0.z += p0.z * w0; a0.w += p0.w * w0;
        a1.x += p1.x * w0; a1.y += p1.y * w0; a1.z += p1.z * w0; a1.w += p1.w * w0;
    }

    float4 bb0 = *reinterpret_cast<const float4*>(&b1[lane * 4]);
    float4 bb1 = *reinterpret_cast<const float4*>(&b1[128 + lane * 4]);
    float rr[8];
    rr[0] = fmaxf(a0.x + bb0.x, 0.f); rr[1] = fmaxf(a0.y + bb0.y, 0.f);
    rr[2] = fmaxf(a0.z + bb0.z, 0.f); rr[3] = fmaxf(a0.w + bb0.w, 0.f);
    rr[4] = fmaxf(a1.x + bb1.x, 0.f); rr[5] = fmaxf(a1.y + bb1.y, 0.f);
    rr[6] = fmaxf(a1.z + bb1.z, 0.f); rr[7] = fmaxf(a1.w + bb1.w, 0.f);

    __nv_bfloat16 h[8], l[8];
#pragma unroll
    for (int t = 0; t < 8; t++) {
        h[t] = __float2bfloat16(rr[t]);
        l[t] = __float2bfloat16(rr[t] - __bfloat162float(h[t]));
    }
    size_t base = (size_t)node * HIDDEN;
    __nv_bfloat16* HI = g_h1hi + base;
    __nv_bfloat16* LO = g_h1lo + base;
    *reinterpret_cast<__nv_bfloat162*>(HI + lane * 4)           = __halves2bfloat162(h[0], h[1]);
    *reinterpret_cast<__nv_bfloat162*>(HI + lane * 4 + 2)       = __halves2bfloat162(h[2], h[3]);
    *reinterpret_cast<__nv_bfloat162*>(HI + 128 + lane * 4)     = __halves2bfloat162(h[4], h[5]);
    *reinterpret_cast<__nv_bfloat162*>(HI + 128 + lane * 4 + 2) = __halves2bfloat162(h[6], h[7]);
    *reinterpret_cast<__nv_bfloat162*>(LO + lane * 4)           = __halves2bfloat162(l[0], l[1]);
    *reinterpret_cast<__nv_bfloat162*>(LO + lane * 4 + 2)       = __halves2bfloat162(l[2], l[3]);
    *reinterpret_cast<__nv_bfloat162*>(LO + 128 + lane * 4)     = __halves2bfloat162(l[4], l[5]);
    *reinterpret_cast<__nv_bfloat162*>(LO + 128 + lane * 4 + 2) = __halves2bfloat162(l[6], l[7]);
}

__global__ __launch_bounds__(128) void k_agg2(const float* __restrict__ b2,
                                              float* __restrict__ out) {
    int node = blockIdx.x * 4 + (threadIdx.x >> 5);
    if (node >= N_NODES) return;
    int lane = threadIdx.x & 31;
    float wd = g_dinv[node];
    float sw = wd * wd;

    const float* hn = &g_H2[(size_t)node * OUT_FEATS];
    float4 v0 = *reinterpret_cast<const float4*>(&hn[lane * 4]);
    float4 a0 = make_float4(v0.x * sw, v0.y * sw, v0.z * sw, v0.w * sw);

    int beg = g_off[node], end = g_off[node + 1];
    int i = beg;
    for (; i + 1 < end; i += 2) {
        int s0 = g_csr_src[i];
        int s1 = g_csr_src[i + 1];
        float w0 = g_dinv[s0] * wd;
        float w1 = g_dinv[s1] * wd;
        float4 p0 = *reinterpret_cast<const float4*>(&g_H2[(size_t)s0 * OUT_FEATS + lane * 4]);
        float4 q0 = *reinterpret_cast<const float4*>(&g_H2[(size_t)s1 * OUT_FEATS + lane * 4]);
        a0.x += p0.x * w0; a0.y += p0.y * w0; a0.z += p0.z * w0; a0.w += p0.w * w0;
        a0.x += q0.x * w1; a0.y += q0.y * w1; a0.z += q0.z * w1; a0.w += q0.w * w1;
    }
    if (i < end) {
        int s0 = g_csr_src[i];
        float w0 = g_dinv[s0] * wd;
        float4 p0 = *reinterpret_cast<const float4*>(&g_H2[(size_t)s0 * OUT_FEATS + lane * 4]);
        a0.x += p0.x * w0; a0.y += p0.y * w0; a0.z += p0.z * w0; a0.w += p0.w * w0;
    }

    float4 bb = *reinterpret_cast<const float4*>(&b2[lane * 4]);
    *reinterpret_cast<float4*>(&out[(size_t)node * OUT_FEATS + lane * 4]) =
        make_float4(a0.x + bb.x, a0.y + bb.y, a0.z + bb.z, a0.w + bb.w);
}

// ------------------------------------------------------------------------
// launch
// ------------------------------------------------------------------------
extern "C" void kernel_launch(void* const* d_in, const int* in_sizes, int n_in,
                              void* d_out, int out_size) {
    const float* x  = (const float*)d_in[0];
    const int*   ei = (const int*)d_in[1];
    const float* W1 = (const float*)d_in[2];
    const float* b1 = (const float*)d_in[3];
    const float* W2 = (const float*)d_in[4];
    const float* b2 = (const float*)d_in[5];
    float* out = (float*)d_out;

    const int* src = ei;
    const int* dst = ei + N_EDGES;

    __nv_bfloat16 *xhi, *xlo, *w1hi, *w1lo, *h1hi, *h1lo, *w2hi, *w2lo;
    float *H1, *H2;
    cudaGetSymbolAddress((void**)&xhi,  g_xhi);
    cudaGetSymbolAddress((void**)&xlo,  g_xlo);
    cudaGetSymbolAddress((void**)&w1hi, g_w1hi);
    cudaGetSymbolAddress((void**)&w1lo, g_w1lo);
    cudaGetSymbolAddress((void**)&h1hi, g_h1hi);
    cudaGetSymbolAddress((void**)&h1lo, g_h1lo);
    cudaGetSymbolAddress((void**)&w2hi, g_w2hi);
    cudaGetSymbolAddress((void**)&w2lo, g_w2lo);
    cudaGetSymbolAddress((void**)&H1,  g_H1);
    cudaGetSymbolAddress((void**)&H2,  g_H2);

    cudaFuncSetAttribute(k_mma<IN_FEATS>, cudaFuncAttributeMaxDynamicSharedMemorySize, SMEMB);
    cudaFuncSetAttribute(k_mma<HIDDEN>,   cudaFuncAttributeMaxDynamicSharedMemorySize, SMEMB);

    // CSR build
    k_zero_cnt<<<(N_NODES + 255) / 256, 256>>>();
    k_count<<<(N_EDGES / 4 + 255) / 256, 256>>>(dst);
    k_scan<<<1, 1024>>>();
    k_fill<<<(N_EDGES / 4 + 255) / 256, 256>>>(src, dst);

    // split inputs & weights to bf16 hi/lo
    {
        size_t total4 = (size_t)M_PAD * IN_FEATS / 4;
        k_split<IN_FEATS><<<(unsigned)((total4 + 255) / 256), 256>>>(x, N_NODES, xhi, xlo);
    }
    k_split_wT<<<(HIDDEN * IN_FEATS + 255) / 256, 256>>>(W1, IN_FEATS, HIDDEN, w1hi, w1lo);
    k_split_wT<<<(OUT_FEATS * HIDDEN + 255) / 256, 256>>>(W2, HIDDEN, OUT_FEATS, w2hi, w2lo);

    // layer 1: tensor-core GEMM then gather-aggregate (fused bf16 split)
    k_mma<IN_FEATS><<<dim3(HIDDEN / 128, M_PAD / 128), 256, SMEMB>>>(
        xhi, xlo, w1hi, w1lo, H1, HIDDEN);
    k_agg1<<<(N_NODES + 3) / 4, 128>>>(b1);

    // layer 2
    k_mma<HIDDEN><<<dim3(OUT_FEATS / 128, M_PAD / 128), 256, SMEMB>>>(
        h1hi, h1lo, w2hi, w2lo, H2, OUT_FEATS);
    k_agg2<<<(N_NODES + 3) / 4, 128>>>(b2, out);
}

// round 5
// speedup vs baseline: 2.0747x; 1.1409x over previous
#include <cuda_runtime.h>
#include <cuda_fp16.h>
#include <cstdint>

#define N_NODES 50000
#define M_PAD   50048              // N_NODES padded to multiple of 128
#define N_EDGES 800000
#define IN_FEATS 768
#define HIDDEN 256
#define OUT_FEATS 128

// ------------------------------------------------------------------------
// device scratch (no allocation allowed; zero-initialized at module load)
// ------------------------------------------------------------------------
__device__ int   g_cnt[N_NODES];
__device__ int   g_off[N_NODES + 1];
__device__ int   g_cur[N_NODES];
__device__ int   g_csr_src[N_EDGES];
__device__ float g_dinv[N_NODES];

__device__ __half g_xhi[(size_t)M_PAD * IN_FEATS];
__device__ __half g_xlo[(size_t)M_PAD * IN_FEATS];
__device__ __half g_w1h[HIDDEN * IN_FEATS];      // W1^T [256][768] fp16
__device__ __half g_h1hi[(size_t)M_PAD * HIDDEN];   // pad rows stay 0
__device__ __half g_h1lo[(size_t)M_PAD * HIDDEN];
__device__ __half g_w2h[OUT_FEATS * HIDDEN];     // W2^T [128][256] fp16

__device__ float g_H1 [(size_t)M_PAD * HIDDEN];     // X @ W1 (padded rows)
__device__ float g_H2 [(size_t)M_PAD * OUT_FEATS];  // agg(H1) @ W2

// ------------------------------------------------------------------------
// PTX helpers (plain sm_80/90-level: harness PTX target lacks the 'a' set)
// ------------------------------------------------------------------------
__device__ __forceinline__ uint32_t smem_u32(const void* p) {
    uint32_t a;
    asm("{ .reg .u64 t; cvta.to.shared.u64 t, %1; cvt.u32.u64 %0, t; }"
        : "=r"(a) : "l"(p));
    return a;
}

__device__ __forceinline__ void cp16(uint32_t dst, const void* src) {
    asm volatile("cp.async.cg.shared.global [%0], [%1], 16;" :: "r"(dst), "l"(src) : "memory");
}

__device__ __forceinline__ void ldsm_x4(uint32_t* r, uint32_t addr) {
    asm volatile("ldmatrix.sync.aligned.m8n8.x4.shared.b16 {%0,%1,%2,%3}, [%4];"
                 : "=r"(r[0]), "=r"(r[1]), "=r"(r[2]), "=r"(r[3]) : "r"(addr));
}

__device__ __forceinline__ void mma_f16(float* d, const uint32_t* a, const uint32_t* b) {
    asm volatile(
        "mma.sync.aligned.m16n8k16.row.col.f32.f16.f16.f32 "
        "{%0,%1,%2,%3}, {%4,%5,%6,%7}, {%8,%9}, {%0,%1,%2,%3};"
        : "+f"(d[0]), "+f"(d[1]), "+f"(d[2]), "+f"(d[3])
        : "r"(a[0]), "r"(a[1]), "r"(a[2]), "r"(a[3]), "r"(b[0]), "r"(b[1]));
}

// ------------------------------------------------------------------------
// CSR build
// ------------------------------------------------------------------------
__global__ void k_zero_cnt() {
    int i = blockIdx.x * blockDim.x + threadIdx.x;
    if (i < N_NODES) g_cnt[i] = 0;
}

__global__ void k_count(const int* __restrict__ dst) {
    int e4 = blockIdx.x * blockDim.x + threadIdx.x;
    if (e4 * 4 < N_EDGES) {
        int4 d = *reinterpret_cast<const int4*>(dst + e4 * 4);
        atomicAdd(&g_cnt[d.x], 1);
        atomicAdd(&g_cnt[d.y], 1);
        atomicAdd(&g_cnt[d.z], 1);
        atomicAdd(&g_cnt[d.w], 1);
    }
}

__global__ void k_scan() {
    __shared__ int partial[1024];
    int t = threadIdx.x;
    const int CH = (N_NODES + 1023) / 1024;
    int begin = t * CH;
    int end = begin + CH; if (end > N_NODES) end = N_NODES;
    int s = 0;
    for (int i = begin; i < end; i++) s += g_cnt[i];
    partial[t] = s;
    __syncthreads();
    for (int ofs = 1; ofs < 1024; ofs <<= 1) {
        int v = (t >= ofs) ? partial[t - ofs] : 0;
        __syncthreads();
        partial[t] += v;
        __syncthreads();
    }
    int run = (t == 0) ? 0 : partial[t - 1];
    for (int i = begin; i < end; i++) {
        g_off[i] = run;
        g_cur[i] = run;
        int c = g_cnt[i];
        g_dinv[i] = rsqrtf((float)(c + 1));
        run += c;
    }
    if (t == 0) g_off[N_NODES] = N_EDGES;
}

__global__ void k_fill(const int* __restrict__ src, const int* __restrict__ dst) {
    int e4 = blockIdx.x * blockDim.x + threadIdx.x;
    if (e4 * 4 < N_EDGES) {
        int4 d = *reinterpret_cast<const int4*>(dst + e4 * 4);
        int4 s = *reinterpret_cast<const int4*>(src + e4 * 4);
        g_csr_src[atomicAdd(&g_cur[d.x], 1)] = s.x;
        g_csr_src[atomicAdd(&g_cur[d.y], 1)] = s.y;
        g_csr_src[atomicAdd(&g_cur[d.z], 1)] = s.z;
        g_csr_src[atomicAdd(&g_cur[d.w], 1)] = s.w;
    }
}

// ------------------------------------------------------------------------
// fp32 -> fp16 (hi, lo) split kernels
// ------------------------------------------------------------------------
template <int F>
__global__ void k_split(const float* __restrict__ src, int nrows_valid,
                        __half* __restrict__ hi_out,
                        __half* __restrict__ lo_out) {
    size_t i4 = (size_t)blockIdx.x * blockDim.x + threadIdx.x;
    const size_t total4 = (size_t)M_PAD * F / 4;
    if (i4 >= total4) return;
    size_t i = i4 * 4;
    int row = (int)(i / F);
    float4 v = make_float4(0.f, 0.f, 0.f, 0.f);
    if (row < nrows_valid) v = *reinterpret_cast<const float4*>(src + i);
    float a[4] = {v.x, v.y, v.z, v.w};
    __half h[4], l[4];
#pragma unroll
    for (int t = 0; t < 4; t++) {
        h[t] = __float2half_rn(a[t]);
        l[t] = __float2half_rn(a[t] - __half2float(h[t]));
    }
    *reinterpret_cast<__half2*>(hi_out + i)     = __halves2half2(h[0], h[1]);
    *reinterpret_cast<__half2*>(hi_out + i + 2) = __halves2half2(h[2], h[3]);
    *reinterpret_cast<__half2*>(lo_out + i)     = __halves2half2(l[0], l[1]);
    *reinterpret_cast<__half2*>(lo_out + i + 2) = __halves2half2(l[2], l[3]);
}

// transpose weights to fp16: W[K][N] -> Wt[N][K]
__global__ void k_wT(const float* __restrict__ W, int K, int N,
                     __half* __restrict__ out) {
    int idx = blockIdx.x * blockDim.x + threadIdx.x;
    if (idx >= N * K) return;
    int n = idx / K, k = idx % K;
    out[idx] = __float2half_rn(W[(size_t)k * N + n]);
}

// ------------------------------------------------------------------------
// fp16 2-term split GEMM via mma.sync m16n8k16:  C = A * B^T
//   C ≈ Ah*Bh + Al*Bh   (B = fp16(W^T), single term)
// CTA tile 128x128, BK=32, 8 warps (warp tile 32x64), 3-stage cp.async,
// 80B-padded smem rows (conflict-free ldsm).
// ------------------------------------------------------------------------
static constexpr int ROWB   = 80;                   // 64B data + 16B pad
static constexpr int TILEB  = 128 * ROWB;           // 10240 per operand tile
static constexpr int STAGEB = 3 * TILEB;            // Ahi, Alo, Bh = 30720
static constexpr int NSTAGE = 3;
static constexpr int SMEMB  = NSTAGE * STAGEB;      // 92160

template <int KTOT>
__device__ __forceinline__ void load_stage(
    uint32_t sb, int tid, int kc, int m0, int n0,
    const __half* __restrict__ Ahi, const __half* __restrict__ Alo,
    const __half* __restrict__ Bh)
{
    const int k0 = kc * 32;
#pragma unroll
    for (int j = 0; j < 6; j++) {                  // 3 tiles * 512 = 1536 / 256
        int linear = j * 256 + tid;
        int tile   = linear >> 9;                  // 0 Ahi, 1 Alo, 2 Bh
        int within = linear & 511;
        int row    = within >> 2;
        int chunk  = within & 3;
        const __half* base = (tile == 0) ? Ahi : (tile == 1) ? Alo : Bh;
        int grow = ((tile < 2) ? m0 : n0) + row;
        const void* g = base + (size_t)grow * KTOT + k0 + chunk * 8;
        cp16(sb + tile * TILEB + row * ROWB + chunk * 16, g);
    }
    asm volatile("cp.async.commit_group;" ::: "memory");
}

template <int KTOT>
__global__ __launch_bounds__(256, 2) void k_mma(
    const __half* __restrict__ Ahi, const __half* __restrict__ Alo,
    const __half* __restrict__ Bh,
    float* __restrict__ C, int ldc)
{
    constexpr int NC = KTOT / 32;
    extern __shared__ __align__(128) char smem[];
    const uint32_t sb0 = smem_u32(smem);
    const int tid  = threadIdx.x;
    const int lane = tid & 31;
    const int wid  = tid >> 5;
    const int wm   = wid & 3;        // 4 warps down M (32 rows each)
    const int wn   = wid >> 2;       // 2 warps across N (64 cols each)
    const int m0 = blockIdx.y * 128, n0 = blockIdx.x * 128;

    float acc[2][8][4];
#pragma unroll
    for (int i = 0; i < 2; i++)
#pragma unroll
        for (int j = 0; j < 8; j++)
#pragma unroll
            for (int q = 0; q < 4; q++) acc[i][j][q] = 0.f;

    const int g = lane >> 3;
    const int r = lane & 7;

    load_stage<KTOT>(sb0, tid, 0, m0, n0, Ahi, Alo, Bh);
    if (NC > 1) load_stage<KTOT>(sb0 + STAGEB, tid, 1, m0, n0, Ahi, Alo, Bh);

    for (int c = 0; c < NC; c++) {
        if (c + 1 < NC) asm volatile("cp.async.wait_group 1;" ::: "memory");
        else            asm volatile("cp.async.wait_group 0;" ::: "memory");
        __syncthreads();

        if (c + 2 < NC)
            load_stage<KTOT>(sb0 + ((c + 2) % NSTAGE) * STAGEB, tid, c + 2,
                             m0, n0, Ahi, Alo, Bh);

        const uint32_t sb = sb0 + (c % NSTAGE) * STAGEB;
#pragma unroll
        for (int kk = 0; kk < 2; kk++) {
            uint32_t ahi[2][4], alo[2][4];
#pragma unroll
            for (int ms = 0; ms < 2; ms++) {
                uint32_t arow = wm * 32 + ms * 16 + ((g & 1) << 3) + r;
                uint32_t aoff = arow * ROWB + kk * 32 + ((g >> 1) << 4);
                ldsm_x4(ahi[ms], sb + aoff);
                ldsm_x4(alo[ms], sb + TILEB + aoff);
            }
#pragma unroll
            for (int nb2 = 0; nb2 < 4; nb2++) {
                uint32_t nrow = wn * 64 + nb2 * 16 + ((g >> 1) << 3) + r;
                uint32_t boff = nrow * ROWB + kk * 32 + ((g & 1) << 4);
                uint32_t bh[4];
                ldsm_x4(bh, sb + 2 * TILEB + boff);
#pragma unroll
                for (int ms = 0; ms < 2; ms++)
#pragma unroll
                    for (int h = 0; h < 2; h++)
                        mma_f16(acc[ms][nb2 * 2 + h], ahi[ms], &bh[h * 2]);
#pragma unroll
                for (int ms = 0; ms < 2; ms++)
#pragma unroll
                    for (int h = 0; h < 2; h++)
                        mma_f16(acc[ms][nb2 * 2 + h], alo[ms], &bh[h * 2]);
            }
        }
        __syncthreads();
    }

#pragma unroll
    for (int ms = 0; ms < 2; ms++) {
        int grow = m0 + wm * 32 + ms * 16 + (lane >> 2);
#pragma unroll
        for (int nb = 0; nb < 8; nb++) {
            int gcol = n0 + wn * 64 + nb * 8 + (lane & 3) * 2;
            *reinterpret_cast<float2*>(&C[(size_t)grow * ldc + gcol]) =
                make_float2(acc[ms][nb][0], acc[ms][nb][1]);
            *reinterpret_cast<float2*>(&C[(size_t)(grow + 8) * ldc + gcol]) =
                make_float2(acc[ms][nb][2], acc[ms][nb][3]);
        }
    }
}

// ------------------------------------------------------------------------
// aggregation: warp-per-node gather-reduce (fp32)
// layer 1: + b1, relu, FUSED fp16 hi/lo split -> g_h1hi/g_h1lo
// ------------------------------------------------------------------------
__global__ __launch_bounds__(128) void k_agg1(const float* __restrict__ b1) {
    int node = blockIdx.x * 4 + (threadIdx.x >> 5);
    if (node >= N_NODES) return;
    int lane = threadIdx.x & 31;
    float wd = g_dinv[node];
    float sw = wd * wd;

    const float* hn = &g_H1[(size_t)node * HIDDEN];
    float4 v0 = *reinterpret_cast<const float4*>(&hn[lane * 4]);
    float4 v1 = *reinterpret_cast<const float4*>(&hn[128 + lane * 4]);
    float4 a0 = make_float4(v0.x * sw, v0.y * sw, v0.z * sw, v0.w * sw);
    float4 a1 = make_float4(v1.x * sw, v1.y * sw, v1.z * sw, v1.w * sw);

    int beg = g_off[node], end = g_off[node + 1];
    int i = beg;
    for (; i + 1 < end; i += 2) {
        int s0 = g_csr_src[i];
        int s1 = g_csr_src[i + 1];
        float w0 = g_dinv[s0] * wd;
        float w1 = g_dinv[s1] * wd;
        const float* h0 = &g_H1[(size_t)s0 * HIDDEN];
        const float* h1 = &g_H1[(size_t)s1 * HIDDEN];
        float4 p0 = *reinterpret_cast<const float4*>(&h0[lane * 4]);
        float4 p1 = *reinterpret_cast<const float4*>(&h0[128 + lane * 4]);
        float4 q0 = *reinterpret_cast<const float4*>(&h1[lane * 4]);
        float4 q1 = *reinterpret_cast<const float4*>(&h1[128 + lane * 4]);
        a0.x += p0.x * w0; a0.y += p0.y * w0; a0.z += p0.z * w0; a0.w += p0.w * w0;
        a1.x += p1.x * w0; a1.y += p1.y * w0; a1.z += p1.z * w0; a1.w += p1.w * w0;
        a0.x += q0.x * w1; a0.y += q0.y * w1; a0.z += q0.z * w1; a0.w += q0.w * w1;
        a1.x += q1.x * w1; a1.y += q1.y * w1; a1.z += q1.z * w1; a1.w += q1.w * w1;
    }
    if (i < end) {
        int s0 = g_csr_src[i];
        float w0 = g_dinv[s0] * wd;
        const float* h0 = &g_H1[(size_t)s0 * HIDDEN];
        float4 p0 = *reinterpret_cast<const float4*>(&h0[lane * 4]);
        float4 p1 = *reinterpret_cast<const float4*>(&h0[128 + lane * 4]);
        a0.x += p0.x * w0; a0.y += p0.y * w0; a0.z += p0.z * w0; a0.w += p0.w * w0;
        a1.x += p1.x * w0; a1.y += p1.y * w0; a1.z += p1.z * w0; a1.w += p1.w * w0;
    }

    float4 bb0 = *reinterpret_cast<const float4*>(&b1[lane * 4]);
    float4 bb1 = *reinterpret_cast<const float4*>(&b1[128 + lane * 4]);
    float rr[8];
    rr[0] = fmaxf(a0.x + bb0.x, 0.f); rr[1] = fmaxf(a0.y + bb0.y, 0.f);
    rr[2] = fmaxf(a0.z + bb0.z, 0.f); rr[3] = fmaxf(a0.w + bb0.w, 0.f);
    rr[4] = fmaxf(a1.x + bb1.x, 0.f); rr[5] = fmaxf(a1.y + bb1.y, 0.f);
    rr[6] = fmaxf(a1.z + bb1.z, 0.f); rr[7] = fmaxf(a1.w + bb1.w, 0.f);

    __half h[8], l[8];
#pragma unroll
    for (int t = 0; t < 8; t++) {
        h[t] = __float2half_rn(rr[t]);
        l[t] = __float2half_rn(rr[t] - __half2float(h[t]));
    }
    size_t base = (size_t)node * HIDDEN;
    __half* HI = g_h1hi + base;
    __half* LO = g_h1lo + base;
    *reinterpret_cast<__half2*>(HI + lane * 4)           = __halves2half2(h[0], h[1]);
    *reinterpret_cast<__half2*>(HI + lane * 4 + 2)       = __halves2half2(h[2], h[3]);
    *reinterpret_cast<__half2*>(HI + 128 + lane * 4)     = __halves2half2(h[4], h[5]);
    *reinterpret_cast<__half2*>(HI + 128 + lane * 4 + 2) = __halves2half2(h[6], h[7]);
    *reinterpret_cast<__half2*>(LO + lane * 4)           = __halves2half2(l[0], l[1]);
    *reinterpret_cast<__half2*>(LO + lane * 4 + 2)       = __halves2half2(l[2], l[3]);
    *reinterpret_cast<__half2*>(LO + 128 + lane * 4)     = __halves2half2(l[4], l[5]);
    *reinterpret_cast<__half2*>(LO + 128 + lane * 4 + 2) = __halves2half2(l[6], l[7]);
}

__global__ __launch_bounds__(128) void k_agg2(const float* __restrict__ b2,
                                              float* __restrict__ out) {
    int node = blockIdx.x * 4 + (threadIdx.x >> 5);
    if (node >= N_NODES) return;
    int lane = threadIdx.x & 31;
    float wd = g_dinv[node];
    float sw = wd * wd;

    const float* hn = &g_H2[(size_t)node * OUT_FEATS];
    float4 v0 = *reinterpret_cast<const float4*>(&hn[lane * 4]);
    float4 a0 = make_float4(v0.x * sw, v0.y * sw, v0.z * sw, v0.w * sw);

    int beg = g_off[node], end = g_off[node + 1];
    int i = beg;
    for (; i + 1 < end; i += 2) {
        int s0 = g_csr_src[i];
        int s1 = g_csr_src[i + 1];
        float w0 = g_dinv[s0] * wd;
        float w1 = g_dinv[s1] * wd;
        float4 p0 = *reinterpret_cast<const float4*>(&g_H2[(size_t)s0 * OUT_FEATS + lane * 4]);
        float4 q0 = *reinterpret_cast<const float4*>(&g_H2[(size_t)s1 * OUT_FEATS + lane * 4]);
        a0.x += p0.x * w0; a0.y += p0.y * w0; a0.z += p0.z * w0; a0.w += p0.w * w0;
        a0.x += q0.x * w1; a0.y += q0.y * w1; a0.z += q0.z * w1; a0.w += q0.w * w1;
    }
    if (i < end) {
        int s0 = g_csr_src[i];
        float w0 = g_dinv[s0] * wd;
        float4 p0 = *reinterpret_cast<const float4*>(&g_H2[(size_t)s0 * OUT_FEATS + lane * 4]);
        a0.x += p0.x * w0; a0.y += p0.y * w0; a0.z += p0.z * w0; a0.w += p0.w * w0;
    }

    float4 bb = *reinterpret_cast<const float4*>(&b2[lane * 4]);
    *reinterpret_cast<float4*>(&out[(size_t)node * OUT_FEATS + lane * 4]) =
        make_float4(a0.x + bb.x, a0.y + bb.y, a0.z + bb.z, a0.w + bb.w);
}

// ------------------------------------------------------------------------
// launch
// ------------------------------------------------------------------------
extern "C" void kernel_launch(void* const* d_in, const int* in_sizes, int n_in,
                              void* d_out, int out_size) {
    const float* x  = (const float*)d_in[0];
    const int*   ei = (const int*)d_in[1];
    const float* W1 = (const float*)d_in[2];
    const float* b1 = (const float*)d_in[3];
    const float* W2 = (const float*)d_in[4];
    const float* b2 = (const float*)d_in[5];
    float* out = (float*)d_out;

    const int* src = ei;
    const int* dst = ei + N_EDGES;

    __half *xhi, *xlo, *w1h, *h1hi, *h1lo, *w2h;
    float *H1, *H2;
    cudaGetSymbolAddress((void**)&xhi,  g_xhi);
    cudaGetSymbolAddress((void**)&xlo,  g_xlo);
    cudaGetSymbolAddress((void**)&w1h,  g_w1h);
    cudaGetSymbolAddress((void**)&h1hi, g_h1hi);
    cudaGetSymbolAddress((void**)&h1lo, g_h1lo);
    cudaGetSymbolAddress((void**)&w2h,  g_w2h);
    cudaGetSymbolAddress((void**)&H1,  g_H1);
    cudaGetSymbolAddress((void**)&H2,  g_H2);

    cudaFuncSetAttribute(k_mma<IN_FEATS>, cudaFuncAttributeMaxDynamicSharedMemorySize, SMEMB);
    cudaFuncSetAttribute(k_mma<HIDDEN>,   cudaFuncAttributeMaxDynamicSharedMemorySize, SMEMB);

    // CSR build
    k_zero_cnt<<<(N_NODES + 255) / 256, 256>>>();
    k_count<<<(N_EDGES / 4 + 255) / 256, 256>>>(dst);
    k_scan<<<1, 1024>>>();
    k_fill<<<(N_EDGES / 4 + 255) / 256, 256>>>(src, dst);

    // split input to fp16 hi/lo; weights to fp16 (transposed)
    {
        size_t total4 = (size_t)M_PAD * IN_FEATS / 4;
        k_split<IN_FEATS><<<(unsigned)((total4 + 255) / 256), 256>>>(x, N_NODES, xhi, xlo);
    }
    k_wT<<<(HIDDEN * IN_FEATS + 255) / 256, 256>>>(W1, IN_FEATS, HIDDEN, w1h);
    k_wT<<<(OUT_FEATS * HIDDEN + 255) / 256, 256>>>(W2, HIDDEN, OUT_FEATS, w2h);

    // layer 1: tensor-core GEMM then gather-aggregate (fused fp16 split)
    k_mma<IN_FEATS><<<dim3(HIDDEN / 128, M_PAD / 128), 256, SMEMB>>>(
        xhi, xlo, w1h, H1, HIDDEN);
    k_agg1<<<(N_NODES + 3) / 4, 128>>>(b1);

    // layer 2
    k_mma<HIDDEN><<<dim3(OUT_FEATS / 128, M_PAD / 128), 256, SMEMB>>>(
        h1hi, h1lo, w2h, H2, OUT_FEATS);
    k_agg2<<<(N_NODES + 3) / 4, 128>>>(b2, out);
}

// round 6
// speedup vs baseline: 3.4747x; 1.6748x over previous
#include <cuda_runtime.h>
#include <cuda_fp16.h>
#include <cstdint>

#define N_NODES 50000
#define M_PAD   50048              // N_NODES padded to multiple of 128
#define N_EDGES 800000
#define IN_FEATS 768
#define HIDDEN 256
#define OUT_FEATS 128
#define SCAN_NBLK ((N_NODES + 255) / 256)   // 196

// ------------------------------------------------------------------------
// device scratch (no allocation allowed; zero-initialized at module load)
// ------------------------------------------------------------------------
__device__ int   g_cnt[N_NODES];
__device__ int   g_off[N_NODES + 1];
__device__ int   g_cur[N_NODES];
__device__ int   g_csr_src[N_EDGES];
__device__ float g_dinv[N_NODES];
__device__ int   g_bsum[SCAN_NBLK];
__device__ int   g_bpre[SCAN_NBLK];

__device__ __half g_xh [(size_t)M_PAD * IN_FEATS];     // fp16(x)
__device__ __half g_w1h[HIDDEN * IN_FEATS];            // fp16(W1^T)
__device__ __half g_h1h[(size_t)M_PAD * HIDDEN];       // fp16(agg1 out); pad rows stay 0
__device__ __half g_w2h[OUT_FEATS * HIDDEN];           // fp16(W2^T)

__device__ float g_H1 [(size_t)M_PAD * HIDDEN];        // X @ W1 (padded rows)
__device__ float g_H2 [(size_t)M_PAD * OUT_FEATS];     // agg(H1) @ W2

// ------------------------------------------------------------------------
// PTX helpers (plain sm_80/90-level: harness PTX target lacks the 'a' set)
// ------------------------------------------------------------------------
__device__ __forceinline__ uint32_t smem_u32(const void* p) {
    uint32_t a;
    asm("{ .reg .u64 t; cvta.to.shared.u64 t, %1; cvt.u32.u64 %0, t; }"
        : "=r"(a) : "l"(p));
    return a;
}

__device__ __forceinline__ void cp16(uint32_t dst, const void* src) {
    asm volatile("cp.async.cg.shared.global [%0], [%1], 16;" :: "r"(dst), "l"(src) : "memory");
}

__device__ __forceinline__ void ldsm_x4(uint32_t* r, uint32_t addr) {
    asm volatile("ldmatrix.sync.aligned.m8n8.x4.shared.b16 {%0,%1,%2,%3}, [%4];"
                 : "=r"(r[0]), "=r"(r[1]), "=r"(r[2]), "=r"(r[3]) : "r"(addr));
}

__device__ __forceinline__ void mma_f16(float* d, const uint32_t* a, const uint32_t* b) {
    asm volatile(
        "mma.sync.aligned.m16n8k16.row.col.f32.f16.f16.f32 "
        "{%0,%1,%2,%3}, {%4,%5,%6,%7}, {%8,%9}, {%0,%1,%2,%3};"
        : "+f"(d[0]), "+f"(d[1]), "+f"(d[2]), "+f"(d[3])
        : "r"(a[0]), "r"(a[1]), "r"(a[2]), "r"(a[3]), "r"(b[0]), "r"(b[1]));
}

// ------------------------------------------------------------------------
// CSR build
// ------------------------------------------------------------------------
__global__ void k_zero_cnt() {
    int i = blockIdx.x * blockDim.x + threadIdx.x;
    if (i < N_NODES) g_cnt[i] = 0;
}

__global__ void k_count(const int* __restrict__ dst) {
    int e4 = blockIdx.x * blockDim.x + threadIdx.x;
    if (e4 * 4 < N_EDGES) {
        int4 d = *reinterpret_cast<const int4*>(dst + e4 * 4);
        atomicAdd(&g_cnt[d.x], 1);
        atomicAdd(&g_cnt[d.y], 1);
        atomicAdd(&g_cnt[d.z], 1);
        atomicAdd(&g_cnt[d.w], 1);
    }
}

// parallel scan, 3 kernels: block sums -> scan of sums -> offsets
__global__ void k_bsum() {
    __shared__ int s[256];
    int t = threadIdx.x;
    int i = blockIdx.x * 256 + t;
    int v = (i < N_NODES) ? g_cnt[i] : 0;
    s[t] = v;
    __syncthreads();
    for (int o = 1; o < 256; o <<= 1) {
        int u = (t >= o) ? s[t - o] : 0;
        __syncthreads();
        s[t] += u;
        __syncthreads();
    }
    if (t == 255) g_bsum[blockIdx.x] = s[255];
}

__global__ void k_bscan() {
    __shared__ int s[256];
    int t = threadIdx.x;
    int v = (t < SCAN_NBLK) ? g_bsum[t] : 0;
    s[t] = v;
    __syncthreads();
    for (int o = 1; o < 256; o <<= 1) {
        int u = (t >= o) ? s[t - o] : 0;
        __syncthreads();
        s[t] += u;
        __syncthreads();
    }
    if (t < SCAN_NBLK) g_bpre[t] = s[t] - v;   // exclusive
}

__global__ void k_off() {
    __shared__ int s[256];
    int t = threadIdx.x;
    int i = blockIdx.x * 256 + t;
    int v = (i < N_NODES) ? g_cnt[i] : 0;
    s[t] = v;
    __syncthreads();
    for (int o = 1; o < 256; o <<= 1) {
        int u = (t >= o) ? s[t - o] : 0;
        __syncthreads();
        s[t] += u;
        __syncthreads();
    }
    if (i < N_NODES) {
        int pre = g_bpre[blockIdx.x] + s[t] - v;
        g_off[i] = pre;
        g_cur[i] = pre;
        g_dinv[i] = rsqrtf((float)(v + 1));
    }
    if (i == 0) g_off[N_NODES] = N_EDGES;
}

__global__ void k_fill(const int* __restrict__ src, const int* __restrict__ dst) {
    int e4 = blockIdx.x * blockDim.x + threadIdx.x;
    if (e4 * 4 < N_EDGES) {
        int4 d = *reinterpret_cast<const int4*>(dst + e4 * 4);
        int4 s = *reinterpret_cast<const int4*>(src + e4 * 4);
        g_csr_src[atomicAdd(&g_cur[d.x], 1)] = s.x;
        g_csr_src[atomicAdd(&g_cur[d.y], 1)] = s.y;
        g_csr_src[atomicAdd(&g_cur[d.z], 1)] = s.z;
        g_csr_src[atomicAdd(&g_cur[d.w], 1)] = s.w;
    }
}

// ------------------------------------------------------------------------
// fp32 -> fp16 convert (X, with M_PAD zero fill)
// ------------------------------------------------------------------------
template <int F>
__global__ void k_conv(const float* __restrict__ src, int nrows_valid,
                       __half* __restrict__ out) {
    size_t i4 = (size_t)blockIdx.x * blockDim.x + threadIdx.x;
    const size_t total4 = (size_t)M_PAD * F / 4;
    if (i4 >= total4) return;
    size_t i = i4 * 4;
    int row = (int)(i / F);
    float4 v = make_float4(0.f, 0.f, 0.f, 0.f);
    if (row < nrows_valid) v = *reinterpret_cast<const float4*>(src + i);
    *reinterpret_cast<__half2*>(out + i)     = __halves2half2(__float2half_rn(v.x), __float2half_rn(v.y));
    *reinterpret_cast<__half2*>(out + i + 2) = __halves2half2(__float2half_rn(v.z), __float2half_rn(v.w));
}

// transpose weights to fp16: W[K][N] -> Wt[N][K]
__global__ void k_wT(const float* __restrict__ W, int K, int N,
                     __half* __restrict__ out) {
    int idx = blockIdx.x * blockDim.x + threadIdx.x;
    if (idx >= N * K) return;
    int n = idx / K, k = idx % K;
    out[idx] = __float2half_rn(W[(size_t)k * N + n]);
}

// ------------------------------------------------------------------------
// fp16 GEMM via mma.sync m16n8k16:  C = A * B^T
// CTA tile 128x128, BK=32, 8 warps (warp tile 32x64), 4-stage cp.async,
// 80B-padded smem rows (conflict-free ldsm).
// ------------------------------------------------------------------------
static constexpr int ROWB   = 80;                   // 64B data + 16B pad
static constexpr int TILEB  = 128 * ROWB;           // 10240 per operand tile
static constexpr int STAGEB = 2 * TILEB;            // A, B = 20480
static constexpr int NSTAGE = 4;
static constexpr int SMEMB  = NSTAGE * STAGEB;      // 81920

template <int KTOT>
__device__ __forceinline__ void load_stage(
    uint32_t sb, int tid, int kc, int m0, int n0,
    const __half* __restrict__ A, const __half* __restrict__ B)
{
    const int k0 = kc * 32;
#pragma unroll
    for (int j = 0; j < 4; j++) {                  // 2 tiles * 512 = 1024 / 256
        int linear = j * 256 + tid;
        int tile   = linear >> 9;                  // 0 A, 1 B
        int within = linear & 511;
        int row    = within >> 2;
        int chunk  = within & 3;
        const __half* base = (tile == 0) ? A : B;
        int grow = ((tile == 0) ? m0 : n0) + row;
        const void* g = base + (size_t)grow * KTOT + k0 + chunk * 8;
        cp16(sb + tile * TILEB + row * ROWB + chunk * 16, g);
    }
    asm volatile("cp.async.commit_group;" ::: "memory");
}

template <int KTOT>
__global__ __launch_bounds__(256, 2) void k_mma(
    const __half* __restrict__ A, const __half* __restrict__ B,
    float* __restrict__ C, int ldc)
{
    constexpr int NC = KTOT / 32;
    extern __shared__ __align__(128) char smem[];
    const uint32_t sb0 = smem_u32(smem);
    const int tid  = threadIdx.x;
    const int lane = tid & 31;
    const int wid  = tid >> 5;
    const int wm   = wid & 3;        // 4 warps down M (32 rows each)
    const int wn   = wid >> 2;       // 2 warps across N (64 cols each)
    const int m0 = blockIdx.y * 128, n0 = blockIdx.x * 128;

    float acc[2][8][4];
#pragma unroll
    for (int i = 0; i < 2; i++)
#pragma unroll
        for (int j = 0; j < 8; j++)
#pragma unroll
            for (int q = 0; q < 4; q++) acc[i][j][q] = 0.f;

    const int g = lane >> 3;
    const int r = lane & 7;

    // prologue: fill 3 of 4 stages
    load_stage<KTOT>(sb0, tid, 0, m0, n0, A, B);
    if (NC > 1) load_stage<KTOT>(sb0 + STAGEB, tid, 1, m0, n0, A, B);
    if (NC > 2) load_stage<KTOT>(sb0 + 2 * STAGEB, tid, 2, m0, n0, A, B);

    for (int c = 0; c < NC; c++) {
        const int rem = NC - 1 - c;          // groups committed after group c
        if (rem >= 2)      asm volatile("cp.async.wait_group 2;" ::: "memory");
        else if (rem == 1) asm volatile("cp.async.wait_group 1;" ::: "memory");
        else               asm volatile("cp.async.wait_group 0;" ::: "memory");
        __syncthreads();

        if (c + 3 < NC)
            load_stage<KTOT>(sb0 + ((c + 3) % NSTAGE) * STAGEB, tid, c + 3,
                             m0, n0, A, B);

        const uint32_t sb = sb0 + (c % NSTAGE) * STAGEB;
#pragma unroll
        for (int kk = 0; kk < 2; kk++) {
            uint32_t af[2][4];
#pragma unroll
            for (int ms = 0; ms < 2; ms++) {
                uint32_t arow = wm * 32 + ms * 16 + ((g & 1) << 3) + r;
                uint32_t aoff = arow * ROWB + kk * 32 + ((g >> 1) << 4);
                ldsm_x4(af[ms], sb + aoff);
            }
#pragma unroll
            for (int nb2 = 0; nb2 < 4; nb2++) {
                uint32_t nrow = wn * 64 + nb2 * 16 + ((g >> 1) << 3) + r;
                uint32_t boff = nrow * ROWB + kk * 32 + ((g & 1) << 4);
                uint32_t bf[4];
                ldsm_x4(bf, sb + TILEB + boff);
#pragma unroll
                for (int ms = 0; ms < 2; ms++)
#pragma unroll
                    for (int h = 0; h < 2; h++)
                        mma_f16(acc[ms][nb2 * 2 + h], af[ms], &bf[h * 2]);
            }
        }
        __syncthreads();
    }

#pragma unroll
    for (int ms = 0; ms < 2; ms++) {
        int grow = m0 + wm * 32 + ms * 16 + (lane >> 2);
#pragma unroll
        for (int nb = 0; nb < 8; nb++) {
            int gcol = n0 + wn * 64 + nb * 8 + (lane & 3) * 2;
            *reinterpret_cast<float2*>(&C[(size_t)grow * ldc + gcol]) =
                make_float2(acc[ms][nb][0], acc[ms][nb][1]);
            *reinterpret_cast<float2*>(&C[(size_t)(grow + 8) * ldc + gcol]) =
                make_float2(acc[ms][nb][2], acc[ms][nb][3]);
        }
    }
}

// ------------------------------------------------------------------------
// aggregation: warp-per-node gather-reduce (fp32 accumulate)
// layer 1: + b1, relu, fp16 convert -> g_h1h
// ------------------------------------------------------------------------
__global__ __launch_bounds__(128) void k_agg1(const float* __restrict__ b1) {
    int node = blockIdx.x * 4 + (threadIdx.x >> 5);
    if (node >= N_NODES) return;
    int lane = threadIdx.x & 31;
    float wd = g_dinv[node];
    float sw = wd * wd;

    const float* hn = &g_H1[(size_t)node * HIDDEN];
    float4 v0 = *reinterpret_cast<const float4*>(&hn[lane * 4]);
    float4 v1 = *reinterpret_cast<const float4*>(&hn[128 + lane * 4]);
    float4 a0 = make_float4(v0.x * sw, v0.y * sw, v0.z * sw, v0.w * sw);
    float4 a1 = make_float4(v1.x * sw, v1.y * sw, v1.z * sw, v1.w * sw);

    int beg = g_off[node], end = g_off[node + 1];
    int i = beg;
    for (; i + 1 < end; i += 2) {
        int s0 = g_csr_src[i];
        int s1 = g_csr_src[i + 1];
        float w0 = g_dinv[s0] * wd;
        float w1 = g_dinv[s1] * wd;
        const float* h0 = &g_H1[(size_t)s0 * HIDDEN];
        const float* h1 = &g_H1[(size_t)s1 * HIDDEN];
        float4 p0 = *reinterpret_cast<const float4*>(&h0[lane * 4]);
        float4 p1 = *reinterpret_cast<const float4*>(&h0[128 + lane * 4]);
        float4 q0 = *reinterpret_cast<const float4*>(&h1[lane * 4]);
        float4 q1 = *reinterpret_cast<const float4*>(&h1[128 + lane * 4]);
        a0.x += p0.x * w0; a0.y += p0.y * w0; a0.z += p0.z * w0; a0.w += p0.w * w0;
        a1.x += p1.x * w0; a1.y += p1.y * w0; a1.z += p1.z * w0; a1.w += p1.w * w0;
        a0.x += q0.x * w1; a0.y += q0.y * w1; a0.z += q0.z * w1; a0.w += q0.w * w1;
        a1.x += q1.x * w1; a1.y += q1.y * w1; a1.z += q1.z * w1; a1.w += q1.w * w1;
    }
    if (i < end) {
        int s0 = g_csr_src[i];
        float w0 = g_dinv[s0] * wd;
        const float* h0 = &g_H1[(size_t)s0 * HIDDEN];
        float4 p0 = *reinterpret_cast<const float4*>(&h0[lane * 4]);
        float4 p1 = *reinterpret_cast<const float4*>(&h0[128 + lane * 4]);
        a0.x += p0.x * w0; a0.y += p0.y * w0; a0.z += p0.z * w0; a0.w += p0.w * w0;
        a1.x += p1.x * w0; a1.y += p1.y * w0; a1.z += p1.z * w0; a1.w += p1.w * w0;
    }

    float4 bb0 = *reinterpret_cast<const float4*>(&b1[lane * 4]);
    float4 bb1 = *reinterpret_cast<const float4*>(&b1[128 + lane * 4]);
    float rr[8];
    rr[0] = fmaxf(a0.x + bb0.x, 0.f); rr[1] = fmaxf(a0.y + bb0.y, 0.f);
    rr[2] = fmaxf(a0.z + bb0.z, 0.f); rr[3] = fmaxf(a0.w + bb0.w, 0.f);
    rr[4] = fmaxf(a1.x + bb1.x, 0.f); rr[5] = fmaxf(a1.y + bb1.y, 0.f);
    rr[6] = fmaxf(a1.z + bb1.z, 0.f); rr[7] = fmaxf(a1.w + bb1.w, 0.f);

    size_t base = (size_t)node * HIDDEN;
    __half* H = g_h1h + base;
    *reinterpret_cast<__half2*>(H + lane * 4)           = __halves2half2(__float2half_rn(rr[0]), __float2half_rn(rr[1]));
    *reinterpret_cast<__half2*>(H + lane * 4 + 2)       = __halves2half2(__float2half_rn(rr[2]), __float2half_rn(rr[3]));
    *reinterpret_cast<__half2*>(H + 128 + lane * 4)     = __halves2half2(__float2half_rn(rr[4]), __float2half_rn(rr[5]));
    *reinterpret_cast<__half2*>(H + 128 + lane * 4 + 2) = __halves2half2(__float2half_rn(rr[6]), __float2half_rn(rr[7]));
}

__global__ __launch_bounds__(128) void k_agg2(const float* __restrict__ b2,
                                              float* __restrict__ out) {
    int node = blockIdx.x * 4 + (threadIdx.x >> 5);
    if (node >= N_NODES) return;
    int lane = threadIdx.x & 31;
    float wd = g_dinv[node];
    float sw = wd * wd;

    const float* hn = &g_H2[(size_t)node * OUT_FEATS];
    float4 v0 = *reinterpret_cast<const float4*>(&hn[lane * 4]);
    float4 a0 = make_float4(v0.x * sw, v0.y * sw, v0.z * sw, v0.w * sw);

    int beg = g_off[node], end = g_off[node + 1];
    int i = beg;
    for (; i + 1 < end; i += 2) {
        int s0 = g_csr_src[i];
        int s1 = g_csr_src[i + 1];
        float w0 = g_dinv[s0] * wd;
        float w1 = g_dinv[s1] * wd;
        float4 p0 = *reinterpret_cast<const float4*>(&g_H2[(size_t)s0 * OUT_FEATS + lane * 4]);
        float4 q0 = *reinterpret_cast<const float4*>(&g_H2[(size_t)s1 * OUT_FEATS + lane * 4]);
        a0.x += p0.x * w0; a0.y += p0.y * w0; a0.z += p0.z * w0; a0.w += p0.w * w0;
        a0.x += q0.x * w1; a0.y += q0.y * w1; a0.z += q0.z * w1; a0.w += q0.w * w1;
    }
    if (i < end) {
        int s0 = g_csr_src[i];
        float w0 = g_dinv[s0] * wd;
        float4 p0 = *reinterpret_cast<const float4*>(&g_H2[(size_t)s0 * OUT_FEATS + lane * 4]);
        a0.x += p0.x * w0; a0.y += p0.y * w0; a0.z += p0.z * w0; a0.w += p0.w * w0;
    }

    float4 bb = *reinterpret_cast<const float4*>(&b2[lane * 4]);
    *reinterpret_cast<float4*>(&out[(size_t)node * OUT_FEATS + lane * 4]) =
        make_float4(a0.x + bb.x, a0.y + bb.y, a0.z + bb.z, a0.w + bb.w);
}

// ------------------------------------------------------------------------
// launch
// ------------------------------------------------------------------------
extern "C" void kernel_launch(void* const* d_in, const int* in_sizes, int n_in,
                              void* d_out, int out_size) {
    const float* x  = (const float*)d_in[0];
    const int*   ei = (const int*)d_in[1];
    const float* W1 = (const float*)d_in[2];
    const float* b1 = (const float*)d_in[3];
    const float* W2 = (const float*)d_in[4];
    const float* b2 = (const float*)d_in[5];
    float* out = (float*)d_out;

    const int* src = ei;
    const int* dst = ei + N_EDGES;

    __half *xh, *w1h, *h1h, *w2h;
    float *H1, *H2;
    cudaGetSymbolAddress((void**)&xh,  g_xh);
    cudaGetSymbolAddress((void**)&w1h, g_w1h);
    cudaGetSymbolAddress((void**)&h1h, g_h1h);
    cudaGetSymbolAddress((void**)&w2h, g_w2h);
    cudaGetSymbolAddress((void**)&H1,  g_H1);
    cudaGetSymbolAddress((void**)&H2,  g_H2);

    cudaFuncSetAttribute(k_mma<IN_FEATS>, cudaFuncAttributeMaxDynamicSharedMemorySize, SMEMB);
    cudaFuncSetAttribute(k_mma<HIDDEN>,   cudaFuncAttributeMaxDynamicSharedMemorySize, SMEMB);

    // CSR build
    k_zero_cnt<<<(N_NODES + 255) / 256, 256>>>();
    k_count<<<(N_EDGES / 4 + 255) / 256, 256>>>(dst);
    k_bsum<<<SCAN_NBLK, 256>>>();
    k_bscan<<<1, 256>>>();
    k_off<<<SCAN_NBLK, 256>>>();
    k_fill<<<(N_EDGES / 4 + 255) / 256, 256>>>(src, dst);

    // converts
    {
        size_t total4 = (size_t)M_PAD * IN_FEATS / 4;
        k_conv<IN_FEATS><<<(unsigned)((total4 + 255) / 256), 256>>>(x, N_NODES, xh);
    }
    k_wT<<<(HIDDEN * IN_FEATS + 255) / 256, 256>>>(W1, IN_FEATS, HIDDEN, w1h);
    k_wT<<<(OUT_FEATS * HIDDEN + 255) / 256, 256>>>(W2, HIDDEN, OUT_FEATS, w2h);

    // layer 1: tensor-core GEMM then gather-aggregate (fused fp16 convert)
    k_mma<IN_FEATS><<<dim3(HIDDEN / 128, M_PAD / 128), 256, SMEMB>>>(
        xh, w1h, H1, HIDDEN);
    k_agg1<<<(N_NODES + 3) / 4, 128>>>(b1);

    // layer 2
    k_mma<HIDDEN><<<dim3(OUT_FEATS / 128, M_PAD / 128), 256, SMEMB>>>(
        h1h, w2h, H2, OUT_FEATS);
    k_agg2<<<(N_NODES + 3) / 4, 128>>>(b2, out);
}

// round 7
// speedup vs baseline: 3.7905x; 1.0909x over previous
#include <cuda_runtime.h>
#include <cuda_fp16.h>
#include <cstdint>

#define N_NODES 50000
#define M_PAD   50048              // N_NODES padded to multiple of 128
#define N_EDGES 800000
#define IN_FEATS 768
#define HIDDEN 256
#define OUT_FEATS 128
#define SCAN_NBLK ((N_NODES + 255) / 256)   // 196

// ------------------------------------------------------------------------
// device scratch (no allocation allowed; zero-initialized at module load)
// ------------------------------------------------------------------------
__device__ int   g_cnt[N_NODES];
__device__ int   g_off[N_NODES + 1];
__device__ int   g_cur[N_NODES];
__device__ int   g_csr_src[N_EDGES];
__device__ float g_dinv[N_NODES];
__device__ int   g_bsum[SCAN_NBLK];
__device__ int   g_bpre[SCAN_NBLK];

__device__ __half g_xh  [(size_t)M_PAD * IN_FEATS];   // fp16(x)
__device__ __half g_w1h [HIDDEN * IN_FEATS];          // fp16(W1^T)
__device__ __half g_H1h [(size_t)M_PAD * HIDDEN];     // fp16(X @ W1)  pre-agg
__device__ __half g_h1a [(size_t)M_PAD * HIDDEN];     // fp16(relu(agg+b1)); pad rows stay 0
__device__ __half g_w2h [OUT_FEATS * HIDDEN];         // fp16(W2^T)
__device__ __half g_H2h [(size_t)M_PAD * OUT_FEATS];  // fp16(h1a @ W2) pre-agg

// ------------------------------------------------------------------------
// PTX helpers (plain sm_80/90-level: harness PTX target lacks the 'a' set)
// ------------------------------------------------------------------------
__device__ __forceinline__ uint32_t smem_u32(const void* p) {
    uint32_t a;
    asm("{ .reg .u64 t; cvta.to.shared.u64 t, %1; cvt.u32.u64 %0, t; }"
        : "=r"(a) : "l"(p));
    return a;
}

__device__ __forceinline__ void cp16(uint32_t dst, const void* src) {
    asm volatile("cp.async.cg.shared.global [%0], [%1], 16;" :: "r"(dst), "l"(src) : "memory");
}

__device__ __forceinline__ void ldsm_x4(uint32_t* r, uint32_t addr) {
    asm volatile("ldmatrix.sync.aligned.m8n8.x4.shared.b16 {%0,%1,%2,%3}, [%4];"
                 : "=r"(r[0]), "=r"(r[1]), "=r"(r[2]), "=r"(r[3]) : "r"(addr));
}

__device__ __forceinline__ void mma_f16(float* d, const uint32_t* a, const uint32_t* b) {
    asm volatile(
        "mma.sync.aligned.m16n8k16.row.col.f32.f16.f16.f32 "
        "{%0,%1,%2,%3}, {%4,%5,%6,%7}, {%8,%9}, {%0,%1,%2,%3};"
        : "+f"(d[0]), "+f"(d[1]), "+f"(d[2]), "+f"(d[3])
        : "r"(a[0]), "r"(a[1]), "r"(a[2]), "r"(a[3]), "r"(b[0]), "r"(b[1]));
}

// accumulate 8 fp16 (as uint4) scaled by w into a[8]
__device__ __forceinline__ void acc8(float* a, const uint4& u, float w) {
    const __half2* h = reinterpret_cast<const __half2*>(&u);
#pragma unroll
    for (int t = 0; t < 4; t++) {
        float2 f = __half22float2(h[t]);
        a[2 * t]     += f.x * w;
        a[2 * t + 1] += f.y * w;
    }
}

__device__ __forceinline__ void acc4(float* a, const uint2& u, float w) {
    const __half2* h = reinterpret_cast<const __half2*>(&u);
#pragma unroll
    for (int t = 0; t < 2; t++) {
        float2 f = __half22float2(h[t]);
        a[2 * t]     += f.x * w;
        a[2 * t + 1] += f.y * w;
    }
}

// ------------------------------------------------------------------------
// CSR build
// ------------------------------------------------------------------------
__global__ void k_zero_cnt() {
    int i = blockIdx.x * blockDim.x + threadIdx.x;
    if (i < N_NODES) g_cnt[i] = 0;
}

__global__ void k_count(const int* __restrict__ dst) {
    int e4 = blockIdx.x * blockDim.x + threadIdx.x;
    if (e4 * 4 < N_EDGES) {
        int4 d = *reinterpret_cast<const int4*>(dst + e4 * 4);
        atomicAdd(&g_cnt[d.x], 1);
        atomicAdd(&g_cnt[d.y], 1);
        atomicAdd(&g_cnt[d.z], 1);
        atomicAdd(&g_cnt[d.w], 1);
    }
}

// parallel scan, 3 kernels
__global__ void k_bsum() {
    __shared__ int s[256];
    int t = threadIdx.x;
    int i = blockIdx.x * 256 + t;
    int v = (i < N_NODES) ? g_cnt[i] : 0;
    s[t] = v;
    __syncthreads();
    for (int o = 1; o < 256; o <<= 1) {
        int u = (t >= o) ? s[t - o] : 0;
        __syncthreads();
        s[t] += u;
        __syncthreads();
    }
    if (t == 255) g_bsum[blockIdx.x] = s[255];
}

__global__ void k_bscan() {
    __shared__ int s[256];
    int t = threadIdx.x;
    int v = (t < SCAN_NBLK) ? g_bsum[t] : 0;
    s[t] = v;
    __syncthreads();
    for (int o = 1; o < 256; o <<= 1) {
        int u = (t >= o) ? s[t - o] : 0;
        __syncthreads();
        s[t] += u;
        __syncthreads();
    }
    if (t < SCAN_NBLK) g_bpre[t] = s[t] - v;
}

__global__ void k_off() {
    __shared__ int s[256];
    int t = threadIdx.x;
    int i = blockIdx.x * 256 + t;
    int v = (i < N_NODES) ? g_cnt[i] : 0;
    s[t] = v;
    __syncthreads();
    for (int o = 1; o < 256; o <<= 1) {
        int u = (t >= o) ? s[t - o] : 0;
        __syncthreads();
        s[t] += u;
        __syncthreads();
    }
    if (i < N_NODES) {
        int pre = g_bpre[blockIdx.x] + s[t] - v;
        g_off[i] = pre;
        g_cur[i] = pre;
        g_dinv[i] = rsqrtf((float)(v + 1));
    }
    if (i == 0) g_off[N_NODES] = N_EDGES;
}

__global__ void k_fill(const int* __restrict__ src, const int* __restrict__ dst) {
    int e4 = blockIdx.x * blockDim.x + threadIdx.x;
    if (e4 * 4 < N_EDGES) {
        int4 d = *reinterpret_cast<const int4*>(dst + e4 * 4);
        int4 s = *reinterpret_cast<const int4*>(src + e4 * 4);
        g_csr_src[atomicAdd(&g_cur[d.x], 1)] = s.x;
        g_csr_src[atomicAdd(&g_cur[d.y], 1)] = s.y;
        g_csr_src[atomicAdd(&g_cur[d.z], 1)] = s.z;
        g_csr_src[atomicAdd(&g_cur[d.w], 1)] = s.w;
    }
}

// ------------------------------------------------------------------------
// fp32 -> fp16 convert (X, with M_PAD zero fill)
// ------------------------------------------------------------------------
template <int F>
__global__ void k_conv(const float* __restrict__ src, int nrows_valid,
                       __half* __restrict__ out) {
    size_t i4 = (size_t)blockIdx.x * blockDim.x + threadIdx.x;
    const size_t total4 = (size_t)M_PAD * F / 4;
    if (i4 >= total4) return;
    size_t i = i4 * 4;
    int row = (int)(i / F);
    float4 v = make_float4(0.f, 0.f, 0.f, 0.f);
    if (row < nrows_valid) v = *reinterpret_cast<const float4*>(src + i);
    *reinterpret_cast<__half2*>(out + i)     = __floats2half2_rn(v.x, v.y);
    *reinterpret_cast<__half2*>(out + i + 2) = __floats2half2_rn(v.z, v.w);
}

// transpose weights to fp16: W[K][N] -> Wt[N][K]
__global__ void k_wT(const float* __restrict__ W, int K, int N,
                     __half* __restrict__ out) {
    int idx = blockIdx.x * blockDim.x + threadIdx.x;
    if (idx >= N * K) return;
    int n = idx / K, k = idx % K;
    out[idx] = __float2half_rn(W[(size_t)k * N + n]);
}

// ------------------------------------------------------------------------
// fp16 GEMM via mma.sync m16n8k16:  C = A * B^T, fp16 output
// CTA tile 128x128, BK=32, 8 warps, 4-stage cp.async, 80B-padded rows.
// ------------------------------------------------------------------------
static constexpr int ROWB   = 80;
static constexpr int TILEB  = 128 * ROWB;
static constexpr int STAGEB = 2 * TILEB;            // 20480
static constexpr int NSTAGE = 4;
static constexpr int SMEMB  = NSTAGE * STAGEB;      // 81920

template <int KTOT>
__device__ __forceinline__ void load_stage(
    uint32_t sb, int tid, int kc, int m0, int n0,
    const __half* __restrict__ A, const __half* __restrict__ B)
{
    const int k0 = kc * 32;
#pragma unroll
    for (int j = 0; j < 4; j++) {
        int linear = j * 256 + tid;
        int tile   = linear >> 9;
        int within = linear & 511;
        int row    = within >> 2;
        int chunk  = within & 3;
        const __half* base = (tile == 0) ? A : B;
        int grow = ((tile == 0) ? m0 : n0) + row;
        const void* g = base + (size_t)grow * KTOT + k0 + chunk * 8;
        cp16(sb + tile * TILEB + row * ROWB + chunk * 16, g);
    }
    asm volatile("cp.async.commit_group;" ::: "memory");
}

template <int KTOT>
__global__ __launch_bounds__(256, 2) void k_mma(
    const __half* __restrict__ A, const __half* __restrict__ B,
    __half* __restrict__ C, int ldc)
{
    constexpr int NC = KTOT / 32;
    extern __shared__ __align__(128) char smem[];
    const uint32_t sb0 = smem_u32(smem);
    const int tid  = threadIdx.x;
    const int lane = tid & 31;
    const int wid  = tid >> 5;
    const int wm   = wid & 3;
    const int wn   = wid >> 2;
    const int m0 = blockIdx.y * 128, n0 = blockIdx.x * 128;

    float acc[2][8][4];
#pragma unroll
    for (int i = 0; i < 2; i++)
#pragma unroll
        for (int j = 0; j < 8; j++)
#pragma unroll
            for (int q = 0; q < 4; q++) acc[i][j][q] = 0.f;

    const int g = lane >> 3;
    const int r = lane & 7;

    load_stage<KTOT>(sb0, tid, 0, m0, n0, A, B);
    if (NC > 1) load_stage<KTOT>(sb0 + STAGEB, tid, 1, m0, n0, A, B);
    if (NC > 2) load_stage<KTOT>(sb0 + 2 * STAGEB, tid, 2, m0, n0, A, B);

    for (int c = 0; c < NC; c++) {
        const int rem = NC - 1 - c;
        if (rem >= 2)      asm volatile("cp.async.wait_group 2;" ::: "memory");
        else if (rem == 1) asm volatile("cp.async.wait_group 1;" ::: "memory");
        else               asm volatile("cp.async.wait_group 0;" ::: "memory");
        __syncthreads();

        if (c + 3 < NC)
            load_stage<KTOT>(sb0 + ((c + 3) % NSTAGE) * STAGEB, tid, c + 3,
                             m0, n0, A, B);

        const uint32_t sb = sb0 + (c % NSTAGE) * STAGEB;
#pragma unroll
        for (int kk = 0; kk < 2; kk++) {
            uint32_t af[2][4];
#pragma unroll
            for (int ms = 0; ms < 2; ms++) {
                uint32_t arow = wm * 32 + ms * 16 + ((g & 1) << 3) + r;
                uint32_t aoff = arow * ROWB + kk * 32 + ((g >> 1) << 4);
                ldsm_x4(af[ms], sb + aoff);
            }
#pragma unroll
            for (int nb2 = 0; nb2 < 4; nb2++) {
                uint32_t nrow = wn * 64 + nb2 * 16 + ((g >> 1) << 3) + r;
                uint32_t boff = nrow * ROWB + kk * 32 + ((g & 1) << 4);
                uint32_t bf[4];
                ldsm_x4(bf, sb + TILEB + boff);
#pragma unroll
                for (int ms = 0; ms < 2; ms++)
#pragma unroll
                    for (int h = 0; h < 2; h++)
                        mma_f16(acc[ms][nb2 * 2 + h], af[ms], &bf[h * 2]);
            }
        }
        __syncthreads();
    }

#pragma unroll
    for (int ms = 0; ms < 2; ms++) {
        int grow = m0 + wm * 32 + ms * 16 + (lane >> 2);
#pragma unroll
        for (int nb = 0; nb < 8; nb++) {
            int gcol = n0 + wn * 64 + nb * 8 + (lane & 3) * 2;
            *reinterpret_cast<__half2*>(&C[(size_t)grow * ldc + gcol]) =
                __floats2half2_rn(acc[ms][nb][0], acc[ms][nb][1]);
            *reinterpret_cast<__half2*>(&C[(size_t)(grow + 8) * ldc + gcol]) =
                __floats2half2_rn(acc[ms][nb][2], acc[ms][nb][3]);
        }
    }
}

// ------------------------------------------------------------------------
// aggregation: warp-per-node fp16 gather, fp32 accumulate
// layer 1: + b1, relu -> fp16 g_h1a   (one uint4 per lane per row)
// ------------------------------------------------------------------------
__global__ __launch_bounds__(128) void k_agg1(const float* __restrict__ b1) {
    int node = blockIdx.x * 4 + (threadIdx.x >> 5);
    if (node >= N_NODES) return;
    int lane = threadIdx.x & 31;
    float wd = g_dinv[node];

    float a[8];
    {
        uint4 u = *reinterpret_cast<const uint4*>(&g_H1h[(size_t)node * HIDDEN + lane * 8]);
        const __half2* h = reinterpret_cast<const __half2*>(&u);
        float sw = wd * wd;
#pragma unroll
        for (int t = 0; t < 4; t++) {
            float2 f = __half22float2(h[t]);
            a[2 * t]     = f.x * sw;
            a[2 * t + 1] = f.y * sw;
        }
    }

    int beg = g_off[node], end = g_off[node + 1];
    int i = beg;
    for (; i + 1 < end; i += 2) {
        int s0 = g_csr_src[i];
        int s1 = g_csr_src[i + 1];
        float w0 = g_dinv[s0] * wd;
        float w1 = g_dinv[s1] * wd;
        uint4 u0 = *reinterpret_cast<const uint4*>(&g_H1h[(size_t)s0 * HIDDEN + lane * 8]);
        uint4 u1 = *reinterpret_cast<const uint4*>(&g_H1h[(size_t)s1 * HIDDEN + lane * 8]);
        acc8(a, u0, w0);
        acc8(a, u1, w1);
    }
    if (i < end) {
        int s0 = g_csr_src[i];
        float w0 = g_dinv[s0] * wd;
        uint4 u0 = *reinterpret_cast<const uint4*>(&g_H1h[(size_t)s0 * HIDDEN + lane * 8]);
        acc8(a, u0, w0);
    }

    float4 bb0 = *reinterpret_cast<const float4*>(&b1[lane * 8]);
    float4 bb1 = *reinterpret_cast<const float4*>(&b1[lane * 8 + 4]);
    float rr[8];
    rr[0] = fmaxf(a[0] + bb0.x, 0.f); rr[1] = fmaxf(a[1] + bb0.y, 0.f);
    rr[2] = fmaxf(a[2] + bb0.z, 0.f); rr[3] = fmaxf(a[3] + bb0.w, 0.f);
    rr[4] = fmaxf(a[4] + bb1.x, 0.f); rr[5] = fmaxf(a[5] + bb1.y, 0.f);
    rr[6] = fmaxf(a[6] + bb1.z, 0.f); rr[7] = fmaxf(a[7] + bb1.w, 0.f);

    __half2 o[4];
#pragma unroll
    for (int t = 0; t < 4; t++) o[t] = __floats2half2_rn(rr[2 * t], rr[2 * t + 1]);
    *reinterpret_cast<uint4*>(&g_h1a[(size_t)node * HIDDEN + lane * 8]) =
        *reinterpret_cast<const uint4*>(o);
}

// layer 2: + b2 -> fp32 out  (one uint2 per lane per row)
__global__ __launch_bounds__(128) void k_agg2(const float* __restrict__ b2,
                                              float* __restrict__ out) {
    int node = blockIdx.x * 4 + (threadIdx.x >> 5);
    if (node >= N_NODES) return;
    int lane = threadIdx.x & 31;
    float wd = g_dinv[node];

    float a[4];
    {
        uint2 u = *reinterpret_cast<const uint2*>(&g_H2h[(size_t)node * OUT_FEATS + lane * 4]);
        const __half2* h = reinterpret_cast<const __half2*>(&u);
        float sw = wd * wd;
#pragma unroll
        for (int t = 0; t < 2; t++) {
            float2 f = __half22float2(h[t]);
            a[2 * t]     = f.x * sw;
            a[2 * t + 1] = f.y * sw;
        }
    }

    int beg = g_off[node], end = g_off[node + 1];
    int i = beg;
    for (; i + 1 < end; i += 2) {
        int s0 = g_csr_src[i];
        int s1 = g_csr_src[i + 1];
        float w0 = g_dinv[s0] * wd;
        float w1 = g_dinv[s1] * wd;
        uint2 u0 = *reinterpret_cast<const uint2*>(&g_H2h[(size_t)s0 * OUT_FEATS + lane * 4]);
        uint2 u1 = *reinterpret_cast<const uint2*>(&g_H2h[(size_t)s1 * OUT_FEATS + lane * 4]);
        acc4(a, u0, w0);
        acc4(a, u1, w1);
    }
    if (i < end) {
        int s0 = g_csr_src[i];
        float w0 = g_dinv[s0] * wd;
        uint2 u0 = *reinterpret_cast<const uint2*>(&g_H2h[(size_t)s0 * OUT_FEATS + lane * 4]);
        acc4(a, u0, w0);
    }

    float4 bb = *reinterpret_cast<const float4*>(&b2[lane * 4]);
    *reinterpret_cast<float4*>(&out[(size_t)node * OUT_FEATS + lane * 4]) =
        make_float4(a[0] + bb.x, a[1] + bb.y, a[2] + bb.z, a[3] + bb.w);
}

// ------------------------------------------------------------------------
// launch
// ------------------------------------------------------------------------
extern "C" void kernel_launch(void* const* d_in, const int* in_sizes, int n_in,
                              void* d_out, int out_size) {
    const float* x  = (const float*)d_in[0];
    const int*   ei = (const int*)d_in[1];
    const float* W1 = (const float*)d_in[2];
    const float* b1 = (const float*)d_in[3];
    const float* W2 = (const float*)d_in[4];
    const float* b2 = (const float*)d_in[5];
    float* out = (float*)d_out;

    const int* src = ei;
    const int* dst = ei + N_EDGES;

    __half *xh, *w1h, *H1h, *h1a, *w2h, *H2h;
    cudaGetSymbolAddress((void**)&xh,  g_xh);
    cudaGetSymbolAddress((void**)&w1h, g_w1h);
    cudaGetSymbolAddress((void**)&H1h, g_H1h);
    cudaGetSymbolAddress((void**)&h1a, g_h1a);
    cudaGetSymbolAddress((void**)&w2h, g_w2h);
    cudaGetSymbolAddress((void**)&H2h, g_H2h);

    cudaFuncSetAttribute(k_mma<IN_FEATS>, cudaFuncAttributeMaxDynamicSharedMemorySize, SMEMB);
    cudaFuncSetAttribute(k_mma<HIDDEN>,   cudaFuncAttributeMaxDynamicSharedMemorySize, SMEMB);

    // CSR build
    k_zero_cnt<<<(N_NODES + 255) / 256, 256>>>();
    k_count<<<(N_EDGES / 4 + 255) / 256, 256>>>(dst);
    k_bsum<<<SCAN_NBLK, 256>>>();
    k_bscan<<<1, 256>>>();
    k_off<<<SCAN_NBLK, 256>>>();
    k_fill<<<(N_EDGES / 4 + 255) / 256, 256>>>(src, dst);

    // converts
    {
        size_t total4 = (size_t)M_PAD * IN_FEATS / 4;
        k_conv<IN_FEATS><<<(unsigned)((total4 + 255) / 256), 256>>>(x, N_NODES, xh);
    }
    k_wT<<<(HIDDEN * IN_FEATS + 255) / 256, 256>>>(W1, IN_FEATS, HIDDEN, w1h);
    k_wT<<<(OUT_FEATS * HIDDEN + 255) / 256, 256>>>(W2, HIDDEN, OUT_FEATS, w2h);

    // layer 1
    k_mma<IN_FEATS><<<dim3(HIDDEN / 128, M_PAD / 128), 256, SMEMB>>>(
        xh, w1h, H1h, HIDDEN);
    k_agg1<<<(N_NODES + 3) / 4, 128>>>(b1);

    // layer 2
    k_mma<HIDDEN><<<dim3(OUT_FEATS / 128, M_PAD / 128), 256, SMEMB>>>(
        h1a, w2h, H2h, OUT_FEATS);
    k_agg2<<<(N_NODES + 3) / 4, 128>>>(b2, out);
}